// round 6
// baseline (speedup 1.0000x reference)
#include <cuda_runtime.h>
#include <math.h>
#include <stdint.h>

// Model dims
#define BT   2
#define TT   2048
#define NTOK 4096
#define DM   512
#define NH   8
#define HSZ  64
#define FFD  2048
#define NL   6
#define VOC  32000

// Scratch
__device__ float g_x [NTOK * DM];
__device__ float g_h [NTOK * DM];
__device__ float g_q [NTOK * DM];
__device__ float g_k [NTOK * DM];
__device__ float g_v [NTOK * DM];
__device__ float g_a [NTOK * DM];
__device__ float g_ff[NTOK * FFD];
__device__ float g_red[2];
__device__ float g_logits_fb[(size_t)NTOK * VOC];

// ---------------------------------------------------------------------------
__device__ __forceinline__ float warpSum(float v) {
#pragma unroll
    for (int o = 16; o > 0; o >>= 1) v += __shfl_xor_sync(0xffffffffu, v, o);
    return v;
}
__device__ __forceinline__ float warpMax(float v) {
#pragma unroll
    for (int o = 16; o > 0; o >>= 1) v = fmaxf(v, __shfl_xor_sync(0xffffffffu, v, o));
    return v;
}

// ---------------------------------------------------------------------------
__global__ void embed_kernel(const int* __restrict__ toks,
                             const float* __restrict__ temb,
                             const float* __restrict__ pemb,
                             float* __restrict__ x) {
    int i = blockIdx.x * blockDim.x + threadIdx.x;
    if (i >= NTOK * DM / 4) return;
    int n  = i / (DM / 4);
    int c  = i % (DM / 4);
    int tk = toks[n];
    int t  = n % TT;
    float4 a = ((const float4*)temb)[(size_t)tk * (DM / 4) + c];
    float4 p = ((const float4*)pemb)[(size_t)t  * (DM / 4) + c];
    float4 r;
    r.x = a.x + p.x; r.y = a.y + p.y; r.z = a.z + p.z; r.w = a.w + p.w;
    ((float4*)x)[i] = r;
}

// ---------------------------------------------------------------------------
__global__ void ln_kernel(const float* __restrict__ in, float* __restrict__ out,
                          const float* __restrict__ gamma, const float* __restrict__ beta) {
    int row = blockIdx.x;
    int tid = threadIdx.x;
    const float4 v4 = ((const float4*)(in + (size_t)row * DM))[tid];
    float s  = v4.x + v4.y + v4.z + v4.w;
    float s2 = v4.x * v4.x + v4.y * v4.y + v4.z * v4.z + v4.w * v4.w;

    __shared__ float rs[4], rs2[4];
    int warp = tid >> 5, lane = tid & 31;
    s = warpSum(s); s2 = warpSum(s2);
    if (lane == 0) { rs[warp] = s; rs2[warp] = s2; }
    __syncthreads();
    float ts = 0.f, ts2 = 0.f;
#pragma unroll
    for (int w = 0; w < 4; w++) { ts += rs[w]; ts2 += rs2[w]; }
    float mean = ts * (1.0f / DM);
    float var  = ts2 * (1.0f / DM) - mean * mean;
    float rstd = rsqrtf(var + 1e-5f);

    float4 g4 = ((const float4*)gamma)[tid];
    float4 b4 = ((const float4*)beta)[tid];
    float4 o;
    o.x = (v4.x - mean) * rstd * g4.x + b4.x;
    o.y = (v4.y - mean) * rstd * g4.y + b4.y;
    o.z = (v4.z - mean) * rstd * g4.z + b4.z;
    o.w = (v4.w - mean) * rstd * g4.w + b4.w;
    ((float4*)(out + (size_t)row * DM))[tid] = o;
}

// ---------------------------------------------------------------------------
// 3xTF32 tensor-core GEMM (fp32-accurate): C = A @ B (+bias,+res,relu)
// Template MT: BM = MT*64 (MT=2: 128x64 tile, MT=1: 64x64 tile for higher
// occupancy / more blocks on small-N GEMMs). BN=64, BK=32. 256 threads.
// QKV=1: blockIdx.z selects one of 3 weight/out pairs (merged QKV launch).
// ---------------------------------------------------------------------------
#define ASTR 36
#define BSTR 72

__device__ __forceinline__ void cpa16(uint32_t s, const void* g) {
    asm volatile("cp.async.cg.shared.global [%0], [%1], 16;\n" :: "r"(s), "l"(g));
}

__device__ __forceinline__ unsigned f2tf(float x) {
    unsigned r;
    asm("cvt.rna.tf32.f32 %0, %1;\n" : "=r"(r) : "f"(x));
    return r;
}

__device__ __forceinline__ void mma_u(float (&c)[4], const unsigned (&A)[4], const unsigned (&B)[2]) {
    asm volatile(
        "mma.sync.aligned.m16n8k8.row.col.f32.tf32.tf32.f32 "
        "{%0,%1,%2,%3}, {%4,%5,%6,%7}, {%8,%9}, {%0,%1,%2,%3};\n"
        : "+f"(c[0]), "+f"(c[1]), "+f"(c[2]), "+f"(c[3])
        : "r"(A[0]), "r"(A[1]), "r"(A[2]), "r"(A[3]), "r"(B[0]), "r"(B[1]));
}

template<int MT, int BIAS, int RES, int RELU, int QKV>
__global__ void __launch_bounds__(256)
tgemm(const float* __restrict__ A,
      const float* __restrict__ B0, const float* __restrict__ B1, const float* __restrict__ B2,
      const float* __restrict__ bias, const float* __restrict__ res,
      float* __restrict__ C0, float* __restrict__ C1, float* __restrict__ C2,
      int K, int lda, int ldb, int ldc, long bz, long cz) {
    constexpr int BM   = MT * 64;
    constexpr int ABUF = BM * ASTR;
    constexpr int BBUF = 32 * BSTR;

    extern __shared__ float smm[];
    float* sA = smm;
    float* sB = smm + 2 * ABUF;

    const float* B;
    float* C;
    if (QKV) {
        int z = blockIdx.z, sel = z >> 3, head = z & 7;
        const float* Bp = (sel == 0) ? B0 : (sel == 1) ? B1 : B2;
        float*       Cp = (sel == 0) ? C0 : (sel == 1) ? C1 : C2;
        B = Bp + (long)head * bz;
        C = Cp + (long)head * cz;
    } else {
        B = B0 + (long)blockIdx.z * bz;
        C = C0 + (long)blockIdx.z * cz;
    }

    int tid = threadIdx.x;
    int rowBase = blockIdx.y * BM;
    int colBase = blockIdx.x * 64;

    uint32_t sAaddr = (uint32_t)__cvta_generic_to_shared(sA);
    uint32_t sBaddr = (uint32_t)__cvta_generic_to_shared(sB);

    int ntiles = K >> 5;

    {
#pragma unroll
        for (int i = 0; i < 2 * MT; i++) {
            int idx = tid + i * 256;
            int r = idx >> 3, c = (idx & 7) * 4;
            cpa16(sAaddr + (uint32_t)(r * ASTR + c) * 4,
                  A + (size_t)(rowBase + r) * lda + c);
        }
#pragma unroll
        for (int i = 0; i < 2; i++) {
            int idx = tid + i * 256;
            int r = idx >> 4, c = (idx & 15) * 4;
            cpa16(sBaddr + (uint32_t)(r * BSTR + c) * 4,
                  B + (size_t)r * ldb + colBase + c);
        }
        asm volatile("cp.async.commit_group;\n");
    }

    float acc[MT][4][4] = {};
    int lane = tid & 31, warp = tid >> 5;
    int wm = warp >> 1, wn = warp & 1;
    int g = lane >> 2, tg = lane & 3;

    for (int t = 0; t < ntiles; t++) {
        asm volatile("cp.async.wait_group 0;\n");
        __syncthreads();
        int cur = t & 1, nxt = cur ^ 1;

        if (t + 1 < ntiles) {
            int k0 = (t + 1) << 5;
#pragma unroll
            for (int i = 0; i < 2 * MT; i++) {
                int idx = tid + i * 256;
                int r = idx >> 3, c = (idx & 7) * 4;
                cpa16(sAaddr + (uint32_t)(nxt * ABUF + r * ASTR + c) * 4,
                      A + (size_t)(rowBase + r) * lda + k0 + c);
            }
#pragma unroll
            for (int i = 0; i < 2; i++) {
                int idx = tid + i * 256;
                int r = idx >> 4, c = (idx & 15) * 4;
                cpa16(sBaddr + (uint32_t)(nxt * BBUF + r * BSTR + c) * 4,
                      B + (size_t)(k0 + r) * ldb + colBase + c);
            }
            asm volatile("cp.async.commit_group;\n");
        }

        const float* cA = sA + cur * ABUF;
        const float* cB = sB + cur * BBUF;

#pragma unroll
        for (int kk = 0; kk < 4; kk++) {
            float a[MT][4], b[4][2];
#pragma unroll
            for (int mt = 0; mt < MT; mt++) {
                int mb = wm * (MT * 16) + mt * 16;
                a[mt][0] = cA[(mb + g)     * ASTR + kk * 8 + tg];
                a[mt][1] = cA[(mb + 8 + g) * ASTR + kk * 8 + tg];
                a[mt][2] = cA[(mb + g)     * ASTR + kk * 8 + 4 + tg];
                a[mt][3] = cA[(mb + 8 + g) * ASTR + kk * 8 + 4 + tg];
            }
#pragma unroll
            for (int nt = 0; nt < 4; nt++) {
                int nb = wn * 32 + nt * 8;
                b[nt][0] = cB[(kk * 8 + tg)     * BSTR + nb + g];
                b[nt][1] = cB[(kk * 8 + 4 + tg) * BSTR + nb + g];
            }

            unsigned ah[MT][4], al[MT][4], bh[4][2], bl[4][2];
#pragma unroll
            for (int mt = 0; mt < MT; mt++)
#pragma unroll
                for (int i = 0; i < 4; i++) {
                    unsigned hh = f2tf(a[mt][i]);
                    ah[mt][i] = hh;
                    al[mt][i] = f2tf(a[mt][i] - __uint_as_float(hh));
                }
#pragma unroll
            for (int nt = 0; nt < 4; nt++)
#pragma unroll
                for (int i = 0; i < 2; i++) {
                    unsigned hh = f2tf(b[nt][i]);
                    bh[nt][i] = hh;
                    bl[nt][i] = f2tf(b[nt][i] - __uint_as_float(hh));
                }

#pragma unroll
            for (int mt = 0; mt < MT; mt++)
#pragma unroll
                for (int nt = 0; nt < 4; nt++) {
                    mma_u(acc[mt][nt], al[mt], bh[nt]);
                    mma_u(acc[mt][nt], ah[mt], bl[nt]);
                    mma_u(acc[mt][nt], ah[mt], bh[nt]);
                }
        }
        __syncthreads();
    }

#pragma unroll
    for (int mt = 0; mt < MT; mt++) {
#pragma unroll
        for (int nt = 0; nt < 4; nt++) {
            int r0 = rowBase + wm * (MT * 16) + mt * 16 + g;
            int c0 = colBase + wn * 32 + nt * 8 + 2 * tg;
            float bx = 0.f, by = 0.f;
            if (BIAS) { bx = bias[c0]; by = bias[c0 + 1]; }
            size_t o0 = (size_t)r0 * ldc + c0;
            size_t o1 = (size_t)(r0 + 8) * ldc + c0;
            float v0 = acc[mt][nt][0] + bx;
            float v1 = acc[mt][nt][1] + by;
            float v2 = acc[mt][nt][2] + bx;
            float v3 = acc[mt][nt][3] + by;
            if (RES) {
                v0 += res[o0]; v1 += res[o0 + 1];
                v2 += res[o1]; v3 += res[o1 + 1];
            }
            if (RELU) {
                v0 = fmaxf(v0, 0.f); v1 = fmaxf(v1, 0.f);
                v2 = fmaxf(v2, 0.f); v3 = fmaxf(v3, 0.f);
            }
            C[o0] = v0; C[o0 + 1] = v1;
            C[o1] = v2; C[o1 + 1] = v3;
        }
    }
}

#define SMEM_MT1 ((2 * (64  * ASTR + 32 * BSTR)) * 4)   // 36864
#define SMEM_MT2 ((2 * (128 * ASTR + 32 * BSTR)) * 4)   // 55296

// ---------------------------------------------------------------------------
// Flash-style causal attention (fp32), 64 queries per block
// ---------------------------------------------------------------------------
#define QS 65
#define FLASH_SMEM ((4 * 64 * QS + 192) * 4)

__global__ void __launch_bounds__(256)
flash_attn(const float* __restrict__ q, const float* __restrict__ k,
           const float* __restrict__ v, float* __restrict__ out) {
    extern __shared__ float sm[];
    float* sQ = sm;
    float* sK = sQ + 64 * QS;
    float* sV = sK + 64 * QS;
    float* sS = sV + 64 * QS;
    float* sm_m = sS + 64 * QS;
    float* sm_l = sm_m + 64;
    float* sm_a = sm_l + 64;

    int qb = blockIdx.x * 64, h = blockIdx.y, b = blockIdx.z;
    int tid = threadIdx.x;
    int q0 = (tid >> 4) * 4;
    int d0 = (tid & 15) * 4;

    const float* qp = q + (size_t)(b * TT + qb) * DM + h * HSZ;
    for (int i = tid; i < 64 * 64; i += 256) {
        int r = i >> 6, c = i & 63;
        sQ[r * QS + c] = qp[(size_t)r * DM + c] * 0.125f;
    }
    if (tid < 64) { sm_m[tid] = -INFINITY; sm_l[tid] = 0.f; }

    float acc[4][4] = {};
    int nkt = qb >> 6;

    for (int kt = 0; kt <= nkt; kt++) {
        __syncthreads();
        const float* kp = k + (size_t)(b * TT + kt * 64) * DM + h * HSZ;
        const float* vp = v + (size_t)(b * TT + kt * 64) * DM + h * HSZ;
        for (int i = tid; i < 64 * 64; i += 256) {
            int r = i >> 6, c = i & 63;
            sK[r * QS + c] = kp[(size_t)r * DM + c];
            sV[r * QS + c] = vp[(size_t)r * DM + c];
        }
        __syncthreads();

        float s[4][4] = {};
#pragma unroll 8
        for (int d = 0; d < 64; d++) {
            float a0 = sQ[(q0 + 0) * QS + d];
            float a1 = sQ[(q0 + 1) * QS + d];
            float a2 = sQ[(q0 + 2) * QS + d];
            float a3 = sQ[(q0 + 3) * QS + d];
            float b0 = sK[(d0 + 0) * QS + d];
            float b1 = sK[(d0 + 1) * QS + d];
            float b2 = sK[(d0 + 2) * QS + d];
            float b3 = sK[(d0 + 3) * QS + d];
            s[0][0] += a0 * b0; s[0][1] += a0 * b1; s[0][2] += a0 * b2; s[0][3] += a0 * b3;
            s[1][0] += a1 * b0; s[1][1] += a1 * b1; s[1][2] += a1 * b2; s[1][3] += a1 * b3;
            s[2][0] += a2 * b0; s[2][1] += a2 * b1; s[2][2] += a2 * b2; s[2][3] += a2 * b3;
            s[3][0] += a3 * b0; s[3][1] += a3 * b1; s[3][2] += a3 * b2; s[3][3] += a3 * b3;
        }
        bool diag = (kt == nkt);
#pragma unroll
        for (int i = 0; i < 4; i++)
#pragma unroll
            for (int j = 0; j < 4; j++) {
                float sv = s[i][j];
                if (diag && (kt * 64 + d0 + j) > (qb + q0 + i)) sv = -INFINITY;
                sS[(q0 + i) * QS + d0 + j] = sv;
            }
        __syncthreads();

        if (tid < 64) {
            int r = tid;
            float m_old = sm_m[r];
            float mx = m_old;
#pragma unroll 8
            for (int j = 0; j < 64; j++) mx = fmaxf(mx, sS[r * QS + j]);
            float al = __expf(m_old - mx);
            float su = 0.f;
#pragma unroll 8
            for (int j = 0; j < 64; j++) {
                float p = __expf(sS[r * QS + j] - mx);
                sS[r * QS + j] = p;
                su += p;
            }
            sm_l[r] = sm_l[r] * al + su;
            sm_m[r] = mx;
            sm_a[r] = al;
        }
        __syncthreads();

        float al[4];
#pragma unroll
        for (int i = 0; i < 4; i++) al[i] = sm_a[q0 + i];
#pragma unroll
        for (int i = 0; i < 4; i++)
#pragma unroll
            for (int j = 0; j < 4; j++) acc[i][j] *= al[i];
#pragma unroll 8
        for (int kk = 0; kk < 64; kk++) {
            float p0 = sS[(q0 + 0) * QS + kk];
            float p1 = sS[(q0 + 1) * QS + kk];
            float p2 = sS[(q0 + 2) * QS + kk];
            float p3 = sS[(q0 + 3) * QS + kk];
            float v0 = sV[kk * QS + d0 + 0];
            float v1 = sV[kk * QS + d0 + 1];
            float v2 = sV[kk * QS + d0 + 2];
            float v3 = sV[kk * QS + d0 + 3];
            acc[0][0] += p0 * v0; acc[0][1] += p0 * v1; acc[0][2] += p0 * v2; acc[0][3] += p0 * v3;
            acc[1][0] += p1 * v0; acc[1][1] += p1 * v1; acc[1][2] += p1 * v2; acc[1][3] += p1 * v3;
            acc[2][0] += p2 * v0; acc[2][1] += p2 * v1; acc[2][2] += p2 * v2; acc[2][3] += p2 * v3;
            acc[3][0] += p3 * v0; acc[3][1] += p3 * v1; acc[3][2] += p3 * v2; acc[3][3] += p3 * v3;
        }
    }

    float linv[4];
#pragma unroll
    for (int i = 0; i < 4; i++) linv[i] = 1.0f / sm_l[q0 + i];
    float* op = out + (size_t)(b * TT + qb) * DM + h * HSZ;
#pragma unroll
    for (int i = 0; i < 4; i++)
#pragma unroll
        for (int j = 0; j < 4; j++)
            op[(size_t)(q0 + i) * DM + d0 + j] = acc[i][j] * linv[i];
}

// ---------------------------------------------------------------------------
__global__ void zero_kernel(float* red) { red[0] = 0.f; red[1] = 0.f; }

__global__ void loss_kernel(const float* __restrict__ logits, const int* __restrict__ tgt,
                            float* __restrict__ red) {
    int r = blockIdx.x;
    int tid = threadIdx.x;
    int warp = tid >> 5, lane = tid & 31;
    const float* row = logits + (size_t)r * VOC;
    __shared__ float rbuf[8];

    float lmax = -INFINITY;
    for (int c = tid; c < VOC; c += 256) lmax = fmaxf(lmax, row[c]);
    lmax = warpMax(lmax);
    if (lane == 0) rbuf[warp] = lmax;
    __syncthreads();
    float gmax = -INFINITY;
#pragma unroll
    for (int w = 0; w < 8; w++) gmax = fmaxf(gmax, rbuf[w]);
    __syncthreads();

    float lsum = 0.f;
    for (int c = tid; c < VOC; c += 256) lsum += __expf(row[c] - gmax);
    lsum = warpSum(lsum);
    if (lane == 0) rbuf[warp] = lsum;
    __syncthreads();
    if (tid == 0) {
        float gsum = 0.f;
#pragma unroll
        for (int w = 0; w < 8; w++) gsum += rbuf[w];
        int tg = tgt[r];
        float lp = row[tg] - gmax - logf(gsum);
        float m = (tg != 0) ? 1.0f : 0.0f;
        atomicAdd(&red[0], -lp * m);
        atomicAdd(&red[1], m);
    }
}

__global__ void finalize_kernel(const float* __restrict__ red, float* __restrict__ outp) {
    outp[0] = red[0] / red[1];
}

// ---------------------------------------------------------------------------
extern "C" void kernel_launch(void* const* d_in, const int* in_sizes, int n_in,
                              void* d_out, int out_size) {
    const int*   toks = (const int*)d_in[0];
    const int*   tgts = (const int*)d_in[1];
    const float* temb = (const float*)d_in[2];
    const float* pemb = (const float*)d_in[3];
    const float* Wq   = (const float*)d_in[4];
    const float* Wk   = (const float*)d_in[5];
    const float* Wv   = (const float*)d_in[6];
    const float* Wo   = (const float*)d_in[7];
    const float* bo   = (const float*)d_in[8];
    const float* ln1g = (const float*)d_in[9];
    const float* ln1b = (const float*)d_in[10];
    const float* ln2g = (const float*)d_in[11];
    const float* ln2b = (const float*)d_in[12];
    const float* W1   = (const float*)d_in[13];
    const float* b1   = (const float*)d_in[14];
    const float* W2   = (const float*)d_in[15];
    const float* b2   = (const float*)d_in[16];
    const float* lnfg = (const float*)d_in[17];
    const float* lnfb = (const float*)d_in[18];
    const float* Wout = (const float*)d_in[19];
    const float* bout = (const float*)d_in[20];

    float *x, *h, *q, *k, *v, *a, *ff, *red, *lfb;
    cudaGetSymbolAddress((void**)&x,   g_x);
    cudaGetSymbolAddress((void**)&h,   g_h);
    cudaGetSymbolAddress((void**)&q,   g_q);
    cudaGetSymbolAddress((void**)&k,   g_k);
    cudaGetSymbolAddress((void**)&v,   g_v);
    cudaGetSymbolAddress((void**)&a,   g_a);
    cudaGetSymbolAddress((void**)&ff,  g_ff);
    cudaGetSymbolAddress((void**)&red, g_red);
    cudaGetSymbolAddress((void**)&lfb, g_logits_fb);

    cudaFuncSetAttribute((const void*)tgemm<1,0,0,0,1>, cudaFuncAttributeMaxDynamicSharedMemorySize, SMEM_MT1);
    cudaFuncSetAttribute((const void*)tgemm<1,1,1,0,0>, cudaFuncAttributeMaxDynamicSharedMemorySize, SMEM_MT1);
    cudaFuncSetAttribute((const void*)tgemm<2,1,0,1,0>, cudaFuncAttributeMaxDynamicSharedMemorySize, SMEM_MT2);
    cudaFuncSetAttribute((const void*)tgemm<2,1,0,0,0>, cudaFuncAttributeMaxDynamicSharedMemorySize, SMEM_MT2);
    cudaFuncSetAttribute((const void*)flash_attn,       cudaFuncAttributeMaxDynamicSharedMemorySize, FLASH_SMEM);

    embed_kernel<<<(NTOK * DM / 4 + 255) / 256, 256>>>(toks, temb, pemb, x);

    for (int l = 0; l < NL; l++) {
        ln_kernel<<<NTOK, 128>>>(x, h, ln1g + l * DM, ln1b + l * DM);

        // merged QKV: grid.z = 24 (3 matrices x 8 heads), BM=64
        tgemm<1,0,0,0,1><<<dim3(1, NTOK / 64, 24), 256, SMEM_MT1>>>(
            h,
            Wq + (size_t)l * NH * DM * HSZ,
            Wk + (size_t)l * NH * DM * HSZ,
            Wv + (size_t)l * NH * DM * HSZ,
            nullptr, nullptr,
            q, k, v,
            DM, DM, HSZ, DM, (long)DM * HSZ, HSZ);

        flash_attn<<<dim3(TT / 64, NH, BT), 256, FLASH_SMEM>>>(q, k, v, a);

        // Wo + bias + residual (BM=64 for 512 blocks)
        tgemm<1,1,1,0,0><<<dim3(DM / 64, NTOK / 64, 1), 256, SMEM_MT1>>>(
            a, Wo + (size_t)l * DM * DM, nullptr, nullptr,
            bo + l * DM, x, x, nullptr, nullptr,
            DM, DM, DM, DM, 0, 0);

        ln_kernel<<<NTOK, 128>>>(x, h, ln2g + l * DM, ln2b + l * DM);

        // FF1 + bias + relu (BM=128)
        tgemm<2,1,0,1,0><<<dim3(FFD / 64, NTOK / 128, 1), 256, SMEM_MT2>>>(
            h, W1 + (size_t)l * DM * FFD, nullptr, nullptr,
            b1 + (size_t)l * FFD, nullptr, ff, nullptr, nullptr,
            DM, DM, FFD, FFD, 0, 0);
        // FF2 + bias + residual (BM=64)
        tgemm<1,1,1,0,0><<<dim3(DM / 64, NTOK / 64, 1), 256, SMEM_MT1>>>(
            ff, W2 + (size_t)l * FFD * DM, nullptr, nullptr,
            b2 + l * DM, x, x, nullptr, nullptr,
            FFD, FFD, DM, DM, 0, 0);
    }

    ln_kernel<<<NTOK, 128>>>(x, h, lnfg, lnfb);

    const long logitsElems = (long)NTOK * VOC;
    float* logits = ((long)out_size >= logitsElems) ? (float*)d_out : lfb;

    tgemm<2,1,0,0,0><<<dim3(VOC / 64, NTOK / 128, 1), 256, SMEM_MT2>>>(
        h, Wout, nullptr, nullptr,
        bout, nullptr, logits, nullptr, nullptr,
        DM, DM, VOC, VOC, 0, 0);

    if ((long)out_size != logitsElems) {
        zero_kernel<<<1, 1>>>(red);
        loss_kernel<<<NTOK, 256>>>(logits, tgts, red);
        float* lossOut;
        if ((long)out_size > logitsElems)
            lossOut = (float*)d_out + logitsElems;
        else
            lossOut = (float*)d_out + (out_size - 1);
        finalize_kernel<<<1, 1>>>(red, lossOut);
    }
}

// round 7
// speedup vs baseline: 1.0989x; 1.0989x over previous
#include <cuda_runtime.h>
#include <math.h>
#include <stdint.h>

// Model dims
#define BT   2
#define TT   2048
#define NTOK 4096
#define DM   512
#define NH   8
#define HSZ  64
#define FFD  2048
#define NL   6
#define VOC  32000

// Scratch
__device__ float g_x [NTOK * DM];
__device__ float g_h [NTOK * DM];
__device__ float g_q [NTOK * DM];
__device__ float g_k [NTOK * DM];
__device__ float g_v [NTOK * DM];
__device__ float g_a [NTOK * DM];
__device__ float g_ff[NTOK * FFD];
__device__ float g_red[2];
__device__ float g_logits_fb[(size_t)NTOK * VOC];

// ---------------------------------------------------------------------------
__device__ __forceinline__ float warpSum(float v) {
#pragma unroll
    for (int o = 16; o > 0; o >>= 1) v += __shfl_xor_sync(0xffffffffu, v, o);
    return v;
}
__device__ __forceinline__ float warpMax(float v) {
#pragma unroll
    for (int o = 16; o > 0; o >>= 1) v = fmaxf(v, __shfl_xor_sync(0xffffffffu, v, o));
    return v;
}

// ---------------------------------------------------------------------------
__global__ void embed_kernel(const int* __restrict__ toks,
                             const float* __restrict__ temb,
                             const float* __restrict__ pemb,
                             float* __restrict__ x) {
    int i = blockIdx.x * blockDim.x + threadIdx.x;
    if (i >= NTOK * DM / 4) return;
    int n  = i / (DM / 4);
    int c  = i % (DM / 4);
    int tk = toks[n];
    int t  = n % TT;
    float4 a = ((const float4*)temb)[(size_t)tk * (DM / 4) + c];
    float4 p = ((const float4*)pemb)[(size_t)t  * (DM / 4) + c];
    float4 r;
    r.x = a.x + p.x; r.y = a.y + p.y; r.z = a.z + p.z; r.w = a.w + p.w;
    ((float4*)x)[i] = r;
}

// ---------------------------------------------------------------------------
__global__ void ln_kernel(const float* __restrict__ in, float* __restrict__ out,
                          const float* __restrict__ gamma, const float* __restrict__ beta) {
    int row = blockIdx.x;
    int tid = threadIdx.x;
    const float4 v4 = ((const float4*)(in + (size_t)row * DM))[tid];
    float s  = v4.x + v4.y + v4.z + v4.w;
    float s2 = v4.x * v4.x + v4.y * v4.y + v4.z * v4.z + v4.w * v4.w;

    __shared__ float rs[4], rs2[4];
    int warp = tid >> 5, lane = tid & 31;
    s = warpSum(s); s2 = warpSum(s2);
    if (lane == 0) { rs[warp] = s; rs2[warp] = s2; }
    __syncthreads();
    float ts = 0.f, ts2 = 0.f;
#pragma unroll
    for (int w = 0; w < 4; w++) { ts += rs[w]; ts2 += rs2[w]; }
    float mean = ts * (1.0f / DM);
    float var  = ts2 * (1.0f / DM) - mean * mean;
    float rstd = rsqrtf(var + 1e-5f);

    float4 g4 = ((const float4*)gamma)[tid];
    float4 b4 = ((const float4*)beta)[tid];
    float4 o;
    o.x = (v4.x - mean) * rstd * g4.x + b4.x;
    o.y = (v4.y - mean) * rstd * g4.y + b4.y;
    o.z = (v4.z - mean) * rstd * g4.z + b4.z;
    o.w = (v4.w - mean) * rstd * g4.w + b4.w;
    ((float4*)(out + (size_t)row * DM))[tid] = o;
}

// ---------------------------------------------------------------------------
// tf32 helpers
// ---------------------------------------------------------------------------
__device__ __forceinline__ void cpa16(uint32_t s, const void* g) {
    asm volatile("cp.async.cg.shared.global [%0], [%1], 16;\n" :: "r"(s), "l"(g));
}

__device__ __forceinline__ unsigned f2tf(float x) {
    unsigned r;
    asm("cvt.rna.tf32.f32 %0, %1;\n" : "=r"(r) : "f"(x));
    return r;
}

__device__ __forceinline__ void mma_u(float (&c)[4], const unsigned (&A)[4], const unsigned (&B)[2]) {
    asm volatile(
        "mma.sync.aligned.m16n8k8.row.col.f32.tf32.tf32.f32 "
        "{%0,%1,%2,%3}, {%4,%5,%6,%7}, {%8,%9}, {%0,%1,%2,%3};\n"
        : "+f"(c[0]), "+f"(c[1]), "+f"(c[2]), "+f"(c[3])
        : "r"(A[0]), "r"(A[1]), "r"(A[2]), "r"(A[3]), "r"(B[0]), "r"(B[1]));
}

// split float[4] / float[2] into tf32 hi/lo
__device__ __forceinline__ void split4(const float (&a)[4], unsigned (&h)[4], unsigned (&l)[4]) {
#pragma unroll
    for (int i = 0; i < 4; i++) {
        unsigned hh = f2tf(a[i]);
        h[i] = hh;
        l[i] = f2tf(a[i] - __uint_as_float(hh));
    }
}
__device__ __forceinline__ void split2(const float (&a)[2], unsigned (&h)[2], unsigned (&l)[2]) {
#pragma unroll
    for (int i = 0; i < 2; i++) {
        unsigned hh = f2tf(a[i]);
        h[i] = hh;
        l[i] = f2tf(a[i] - __uint_as_float(hh));
    }
}

// ---------------------------------------------------------------------------
// 3xTF32 tensor-core GEMM (fp32-accurate)
// ---------------------------------------------------------------------------
#define ASTR 36
#define BSTR 72

template<int MT, int BIAS, int RES, int RELU, int QKV>
__global__ void __launch_bounds__(256)
tgemm(const float* __restrict__ A,
      const float* __restrict__ B0, const float* __restrict__ B1, const float* __restrict__ B2,
      const float* __restrict__ bias, const float* __restrict__ res,
      float* __restrict__ C0, float* __restrict__ C1, float* __restrict__ C2,
      int K, int lda, int ldb, int ldc, long bz, long cz) {
    constexpr int BM   = MT * 64;
    constexpr int ABUF = BM * ASTR;
    constexpr int BBUF = 32 * BSTR;

    extern __shared__ float smm[];
    float* sA = smm;
    float* sB = smm + 2 * ABUF;

    const float* B;
    float* C;
    if (QKV) {
        int z = blockIdx.z, sel = z >> 3, head = z & 7;
        const float* Bp = (sel == 0) ? B0 : (sel == 1) ? B1 : B2;
        float*       Cp = (sel == 0) ? C0 : (sel == 1) ? C1 : C2;
        B = Bp + (long)head * bz;
        C = Cp + (long)head * cz;
    } else {
        B = B0 + (long)blockIdx.z * bz;
        C = C0 + (long)blockIdx.z * cz;
    }

    int tid = threadIdx.x;
    int rowBase = blockIdx.y * BM;
    int colBase = blockIdx.x * 64;

    uint32_t sAaddr = (uint32_t)__cvta_generic_to_shared(sA);
    uint32_t sBaddr = (uint32_t)__cvta_generic_to_shared(sB);

    int ntiles = K >> 5;

    {
#pragma unroll
        for (int i = 0; i < 2 * MT; i++) {
            int idx = tid + i * 256;
            int r = idx >> 3, c = (idx & 7) * 4;
            cpa16(sAaddr + (uint32_t)(r * ASTR + c) * 4,
                  A + (size_t)(rowBase + r) * lda + c);
        }
#pragma unroll
        for (int i = 0; i < 2; i++) {
            int idx = tid + i * 256;
            int r = idx >> 4, c = (idx & 15) * 4;
            cpa16(sBaddr + (uint32_t)(r * BSTR + c) * 4,
                  B + (size_t)r * ldb + colBase + c);
        }
        asm volatile("cp.async.commit_group;\n");
    }

    float acc[MT][4][4] = {};
    int lane = tid & 31, warp = tid >> 5;
    int wm = warp >> 1, wn = warp & 1;
    int g = lane >> 2, tg = lane & 3;

    for (int t = 0; t < ntiles; t++) {
        asm volatile("cp.async.wait_group 0;\n");
        __syncthreads();
        int cur = t & 1, nxt = cur ^ 1;

        if (t + 1 < ntiles) {
            int k0 = (t + 1) << 5;
#pragma unroll
            for (int i = 0; i < 2 * MT; i++) {
                int idx = tid + i * 256;
                int r = idx >> 3, c = (idx & 7) * 4;
                cpa16(sAaddr + (uint32_t)(nxt * ABUF + r * ASTR + c) * 4,
                      A + (size_t)(rowBase + r) * lda + k0 + c);
            }
#pragma unroll
            for (int i = 0; i < 2; i++) {
                int idx = tid + i * 256;
                int r = idx >> 4, c = (idx & 15) * 4;
                cpa16(sBaddr + (uint32_t)(nxt * BBUF + r * BSTR + c) * 4,
                      B + (size_t)(k0 + r) * ldb + colBase + c);
            }
            asm volatile("cp.async.commit_group;\n");
        }

        const float* cA = sA + cur * ABUF;
        const float* cB = sB + cur * BBUF;

#pragma unroll
        for (int kk = 0; kk < 4; kk++) {
            float a[MT][4], b[4][2];
#pragma unroll
            for (int mt = 0; mt < MT; mt++) {
                int mb = wm * (MT * 16) + mt * 16;
                a[mt][0] = cA[(mb + g)     * ASTR + kk * 8 + tg];
                a[mt][1] = cA[(mb + 8 + g) * ASTR + kk * 8 + tg];
                a[mt][2] = cA[(mb + g)     * ASTR + kk * 8 + 4 + tg];
                a[mt][3] = cA[(mb + 8 + g) * ASTR + kk * 8 + 4 + tg];
            }
#pragma unroll
            for (int nt = 0; nt < 4; nt++) {
                int nb = wn * 32 + nt * 8;
                b[nt][0] = cB[(kk * 8 + tg)     * BSTR + nb + g];
                b[nt][1] = cB[(kk * 8 + 4 + tg) * BSTR + nb + g];
            }

            unsigned ah[MT][4], al[MT][4], bh[4][2], bl[4][2];
#pragma unroll
            for (int mt = 0; mt < MT; mt++) split4(a[mt], ah[mt], al[mt]);
#pragma unroll
            for (int nt = 0; nt < 4; nt++) split2(b[nt], bh[nt], bl[nt]);

#pragma unroll
            for (int mt = 0; mt < MT; mt++)
#pragma unroll
                for (int nt = 0; nt < 4; nt++) {
                    mma_u(acc[mt][nt], al[mt], bh[nt]);
                    mma_u(acc[mt][nt], ah[mt], bl[nt]);
                    mma_u(acc[mt][nt], ah[mt], bh[nt]);
                }
        }
        __syncthreads();
    }

#pragma unroll
    for (int mt = 0; mt < MT; mt++) {
#pragma unroll
        for (int nt = 0; nt < 4; nt++) {
            int r0 = rowBase + wm * (MT * 16) + mt * 16 + g;
            int c0 = colBase + wn * 32 + nt * 8 + 2 * tg;
            float bx = 0.f, by = 0.f;
            if (BIAS) { bx = bias[c0]; by = bias[c0 + 1]; }
            size_t o0 = (size_t)r0 * ldc + c0;
            size_t o1 = (size_t)(r0 + 8) * ldc + c0;
            float v0 = acc[mt][nt][0] + bx;
            float v1 = acc[mt][nt][1] + by;
            float v2 = acc[mt][nt][2] + bx;
            float v3 = acc[mt][nt][3] + by;
            if (RES) {
                v0 += res[o0]; v1 += res[o0 + 1];
                v2 += res[o1]; v3 += res[o1 + 1];
            }
            if (RELU) {
                v0 = fmaxf(v0, 0.f); v1 = fmaxf(v1, 0.f);
                v2 = fmaxf(v2, 0.f); v3 = fmaxf(v3, 0.f);
            }
            C[o0] = v0; C[o0 + 1] = v1;
            C[o1] = v2; C[o1 + 1] = v3;
        }
    }
}

#define SMEM_MT1 ((2 * (64  * ASTR + 32 * BSTR)) * 4)   // 36864
#define SMEM_MT2 ((2 * (128 * ASTR + 32 * BSTR)) * 4)   // 55296

// ---------------------------------------------------------------------------
// MMA flash attention (3xTF32): 64 queries/block, 8 warps (4m x 2n).
// S = Q@K^T via mma (K fragments read from natural [key][d] layout: B_eff[k][n]
// = K[n][k] so the B-frag load indexes sK[(n)*str + k] = A-style pattern).
// Online softmax across all 256 threads (4 threads/row). O = P@V via mma.
// ---------------------------------------------------------------------------
#define QSTR 68
#define KSTR 68
#define VSTR 72
#define PSTR 68
#define FLASH_SMEM ((64 * (QSTR + KSTR + VSTR + PSTR) + 192) * 4)  // 71424

__global__ void __launch_bounds__(256)
flash_mma(const float* __restrict__ q, const float* __restrict__ k,
          const float* __restrict__ v, float* __restrict__ out) {
    extern __shared__ float sm[];
    float* sQ = sm;
    float* sK = sQ + 64 * QSTR;
    float* sV = sK + 64 * KSTR;
    float* sP = sV + 64 * VSTR;
    float* sM  = sP + 64 * PSTR;   // 64
    float* sL  = sM + 64;          // 64
    float* sAl = sL + 64;          // 64

    int qb = blockIdx.x * 64, h = blockIdx.y, b = blockIdx.z;
    int tid = threadIdx.x, lane = tid & 31, warp = tid >> 5;
    int wm = warp >> 1, wn = warp & 1;   // 4 x 2 warp grid
    int g = lane >> 2, tg = lane & 3;

    // load Q (pre-scaled by HS^-0.5)
    const float* qp = q + (size_t)(b * TT + qb) * DM + h * HSZ;
    for (int i = tid; i < 64 * 16; i += 256) {
        int r = i >> 4, c = (i & 15) * 4;
        float4 t = *(const float4*)(qp + (size_t)r * DM + c);
        sQ[r * QSTR + c + 0] = t.x * 0.125f;
        sQ[r * QSTR + c + 1] = t.y * 0.125f;
        sQ[r * QSTR + c + 2] = t.z * 0.125f;
        sQ[r * QSTR + c + 3] = t.w * 0.125f;
    }
    if (tid < 64) { sM[tid] = -INFINITY; sL[tid] = 0.f; }

    float accO[4][4] = {};
    int nkt = qb >> 6;

    for (int kt = 0; kt <= nkt; kt++) {
        __syncthreads();  // protect sK/sV/sP from prior iter reads; covers init
        const float* kp = k + (size_t)(b * TT + kt * 64) * DM + h * HSZ;
        const float* vp = v + (size_t)(b * TT + kt * 64) * DM + h * HSZ;
        for (int i = tid; i < 64 * 16; i += 256) {
            int r = i >> 4, c = (i & 15) * 4;
            float4 tk = *(const float4*)(kp + (size_t)r * DM + c);
            float4 tv = *(const float4*)(vp + (size_t)r * DM + c);
            sK[r * KSTR + c + 0] = tk.x; sK[r * KSTR + c + 1] = tk.y;
            sK[r * KSTR + c + 2] = tk.z; sK[r * KSTR + c + 3] = tk.w;
            sV[r * VSTR + c + 0] = tv.x; sV[r * VSTR + c + 1] = tv.y;
            sV[r * VSTR + c + 2] = tv.z; sV[r * VSTR + c + 3] = tv.w;
        }
        __syncthreads();

        // ---- S = Q @ K^T (warp tile: rows wm*16..+16, cols wn*32..+32) ----
        float accS[4][4] = {};
        int mb = wm * 16;
#pragma unroll
        for (int kk = 0; kk < 8; kk++) {
            float a[4];
            a[0] = sQ[(mb + g)     * QSTR + kk * 8 + tg];
            a[1] = sQ[(mb + 8 + g) * QSTR + kk * 8 + tg];
            a[2] = sQ[(mb + g)     * QSTR + kk * 8 + 4 + tg];
            a[3] = sQ[(mb + 8 + g) * QSTR + kk * 8 + 4 + tg];
            unsigned ah[4], al[4];
            split4(a, ah, al);
#pragma unroll
            for (int nt = 0; nt < 4; nt++) {
                int nb = wn * 32 + nt * 8;
                float bb[2];
                bb[0] = sK[(nb + g) * KSTR + kk * 8 + tg];       // K[key][d]
                bb[1] = sK[(nb + g) * KSTR + kk * 8 + 4 + tg];
                unsigned bh[2], bl[2];
                split2(bb, bh, bl);
                mma_u(accS[nt], al, bh);
                mma_u(accS[nt], ah, bl);
                mma_u(accS[nt], ah, bh);
            }
        }

        // write S to sP with causal mask
        bool dg = (kt == nkt);
        int r0 = mb + g, r1 = r0 + 8;
#pragma unroll
        for (int nt = 0; nt < 4; nt++) {
            int c0 = wn * 32 + nt * 8 + 2 * tg;
            float s0 = accS[nt][0], s1 = accS[nt][1];
            float s2 = accS[nt][2], s3 = accS[nt][3];
            if (dg) {
                int qi0 = qb + r0, qi1 = qb + r1, kc = kt * 64 + c0;
                if (kc     > qi0) s0 = -INFINITY;
                if (kc + 1 > qi0) s1 = -INFINITY;
                if (kc     > qi1) s2 = -INFINITY;
                if (kc + 1 > qi1) s3 = -INFINITY;
            }
            sP[r0 * PSTR + c0] = s0; sP[r0 * PSTR + c0 + 1] = s1;
            sP[r1 * PSTR + c0] = s2; sP[r1 * PSTR + c0 + 1] = s3;
        }
        __syncthreads();

        // ---- online softmax: 4 threads per row ----
        {
            int r = tid >> 2, part = tid & 3;
            float* row = sP + r * PSTR + part * 16;
            float m_old = sM[r];
            float mx = m_old;
#pragma unroll
            for (int j = 0; j < 16; j++) mx = fmaxf(mx, row[j]);
            mx = fmaxf(mx, __shfl_xor_sync(0xffffffffu, mx, 1));
            mx = fmaxf(mx, __shfl_xor_sync(0xffffffffu, mx, 2));
            float su = 0.f;
#pragma unroll
            for (int j = 0; j < 16; j++) {
                float p = __expf(row[j] - mx);
                row[j] = p;
                su += p;
            }
            su += __shfl_xor_sync(0xffffffffu, su, 1);
            su += __shfl_xor_sync(0xffffffffu, su, 2);
            if (part == 0) {
                float alv = __expf(m_old - mx);
                sL[r] = sL[r] * alv + su;
                sM[r] = mx;
                sAl[r] = alv;
            }
        }
        __syncthreads();

        // rescale O accumulators
        {
            float a0 = sAl[r0], a1 = sAl[r1];
#pragma unroll
            for (int nt = 0; nt < 4; nt++) {
                accO[nt][0] *= a0; accO[nt][1] *= a0;
                accO[nt][2] *= a1; accO[nt][3] *= a1;
            }
        }

        // ---- O += P @ V ----
#pragma unroll
        for (int kk = 0; kk < 8; kk++) {
            float a[4];
            a[0] = sP[(mb + g)     * PSTR + kk * 8 + tg];
            a[1] = sP[(mb + 8 + g) * PSTR + kk * 8 + tg];
            a[2] = sP[(mb + g)     * PSTR + kk * 8 + 4 + tg];
            a[3] = sP[(mb + 8 + g) * PSTR + kk * 8 + 4 + tg];
            unsigned ah[4], al[4];
            split4(a, ah, al);
#pragma unroll
            for (int nt = 0; nt < 4; nt++) {
                int nb = wn * 32 + nt * 8;
                float bb[2];
                bb[0] = sV[(kk * 8 + tg)     * VSTR + nb + g];   // V[key][d]
                bb[1] = sV[(kk * 8 + 4 + tg) * VSTR + nb + g];
                unsigned bh[2], bl[2];
                split2(bb, bh, bl);
                mma_u(accO[nt], al, bh);
                mma_u(accO[nt], ah, bl);
                mma_u(accO[nt], ah, bh);
            }
        }
    }

    // epilogue: O /= l
    int r0 = wm * 16 + g, r1 = r0 + 8;
    float li0 = 1.0f / sL[r0], li1 = 1.0f / sL[r1];
    float* op = out + (size_t)(b * TT + qb) * DM + h * HSZ;
#pragma unroll
    for (int nt = 0; nt < 4; nt++) {
        int c0 = wn * 32 + nt * 8 + 2 * tg;
        op[(size_t)r0 * DM + c0]     = accO[nt][0] * li0;
        op[(size_t)r0 * DM + c0 + 1] = accO[nt][1] * li0;
        op[(size_t)r1 * DM + c0]     = accO[nt][2] * li1;
        op[(size_t)r1 * DM + c0 + 1] = accO[nt][3] * li1;
    }
}

// ---------------------------------------------------------------------------
__global__ void zero_kernel(float* red) { red[0] = 0.f; red[1] = 0.f; }

__global__ void loss_kernel(const float* __restrict__ logits, const int* __restrict__ tgt,
                            float* __restrict__ red) {
    int r = blockIdx.x;
    int tid = threadIdx.x;
    int warp = tid >> 5, lane = tid & 31;
    const float* row = logits + (size_t)r * VOC;
    __shared__ float rbuf[8];

    float lmax = -INFINITY;
    for (int c = tid; c < VOC; c += 256) lmax = fmaxf(lmax, row[c]);
    lmax = warpMax(lmax);
    if (lane == 0) rbuf[warp] = lmax;
    __syncthreads();
    float gmax = -INFINITY;
#pragma unroll
    for (int w = 0; w < 8; w++) gmax = fmaxf(gmax, rbuf[w]);
    __syncthreads();

    float lsum = 0.f;
    for (int c = tid; c < VOC; c += 256) lsum += __expf(row[c] - gmax);
    lsum = warpSum(lsum);
    if (lane == 0) rbuf[warp] = lsum;
    __syncthreads();
    if (tid == 0) {
        float gsum = 0.f;
#pragma unroll
        for (int w = 0; w < 8; w++) gsum += rbuf[w];
        int tg = tgt[r];
        float lp = row[tg] - gmax - logf(gsum);
        float m = (tg != 0) ? 1.0f : 0.0f;
        atomicAdd(&red[0], -lp * m);
        atomicAdd(&red[1], m);
    }
}

__global__ void finalize_kernel(const float* __restrict__ red, float* __restrict__ outp) {
    outp[0] = red[0] / red[1];
}

// ---------------------------------------------------------------------------
extern "C" void kernel_launch(void* const* d_in, const int* in_sizes, int n_in,
                              void* d_out, int out_size) {
    const int*   toks = (const int*)d_in[0];
    const int*   tgts = (const int*)d_in[1];
    const float* temb = (const float*)d_in[2];
    const float* pemb = (const float*)d_in[3];
    const float* Wq   = (const float*)d_in[4];
    const float* Wk   = (const float*)d_in[5];
    const float* Wv   = (const float*)d_in[6];
    const float* Wo   = (const float*)d_in[7];
    const float* bo   = (const float*)d_in[8];
    const float* ln1g = (const float*)d_in[9];
    const float* ln1b = (const float*)d_in[10];
    const float* ln2g = (const float*)d_in[11];
    const float* ln2b = (const float*)d_in[12];
    const float* W1   = (const float*)d_in[13];
    const float* b1   = (const float*)d_in[14];
    const float* W2   = (const float*)d_in[15];
    const float* b2   = (const float*)d_in[16];
    const float* lnfg = (const float*)d_in[17];
    const float* lnfb = (const float*)d_in[18];
    const float* Wout = (const float*)d_in[19];
    const float* bout = (const float*)d_in[20];

    float *x, *h, *q, *k, *v, *a, *ff, *red, *lfb;
    cudaGetSymbolAddress((void**)&x,   g_x);
    cudaGetSymbolAddress((void**)&h,   g_h);
    cudaGetSymbolAddress((void**)&q,   g_q);
    cudaGetSymbolAddress((void**)&k,   g_k);
    cudaGetSymbolAddress((void**)&v,   g_v);
    cudaGetSymbolAddress((void**)&a,   g_a);
    cudaGetSymbolAddress((void**)&ff,  g_ff);
    cudaGetSymbolAddress((void**)&red, g_red);
    cudaGetSymbolAddress((void**)&lfb, g_logits_fb);

    cudaFuncSetAttribute((const void*)tgemm<1,0,0,0,1>, cudaFuncAttributeMaxDynamicSharedMemorySize, SMEM_MT1);
    cudaFuncSetAttribute((const void*)tgemm<1,1,1,0,0>, cudaFuncAttributeMaxDynamicSharedMemorySize, SMEM_MT1);
    cudaFuncSetAttribute((const void*)tgemm<2,1,0,1,0>, cudaFuncAttributeMaxDynamicSharedMemorySize, SMEM_MT2);
    cudaFuncSetAttribute((const void*)tgemm<2,1,0,0,0>, cudaFuncAttributeMaxDynamicSharedMemorySize, SMEM_MT2);
    cudaFuncSetAttribute((const void*)flash_mma,        cudaFuncAttributeMaxDynamicSharedMemorySize, FLASH_SMEM);

    embed_kernel<<<(NTOK * DM / 4 + 255) / 256, 256>>>(toks, temb, pemb, x);

    for (int l = 0; l < NL; l++) {
        ln_kernel<<<NTOK, 128>>>(x, h, ln1g + l * DM, ln1b + l * DM);

        // merged QKV: grid.z = 24 (3 matrices x 8 heads), BM=64
        tgemm<1,0,0,0,1><<<dim3(1, NTOK / 64, 24), 256, SMEM_MT1>>>(
            h,
            Wq + (size_t)l * NH * DM * HSZ,
            Wk + (size_t)l * NH * DM * HSZ,
            Wv + (size_t)l * NH * DM * HSZ,
            nullptr, nullptr,
            q, k, v,
            DM, DM, HSZ, DM, (long)DM * HSZ, HSZ);

        flash_mma<<<dim3(TT / 64, NH, BT), 256, FLASH_SMEM>>>(q, k, v, a);

        // Wo + bias + residual
        tgemm<1,1,1,0,0><<<dim3(DM / 64, NTOK / 64, 1), 256, SMEM_MT1>>>(
            a, Wo + (size_t)l * DM * DM, nullptr, nullptr,
            bo + l * DM, x, x, nullptr, nullptr,
            DM, DM, DM, DM, 0, 0);

        ln_kernel<<<NTOK, 128>>>(x, h, ln2g + l * DM, ln2b + l * DM);

        // FF1 + bias + relu
        tgemm<2,1,0,1,0><<<dim3(FFD / 64, NTOK / 128, 1), 256, SMEM_MT2>>>(
            h, W1 + (size_t)l * DM * FFD, nullptr, nullptr,
            b1 + (size_t)l * FFD, nullptr, ff, nullptr, nullptr,
            DM, DM, FFD, FFD, 0, 0);
        // FF2 + bias + residual
        tgemm<1,1,1,0,0><<<dim3(DM / 64, NTOK / 64, 1), 256, SMEM_MT1>>>(
            ff, W2 + (size_t)l * FFD * DM, nullptr, nullptr,
            b2 + l * DM, x, x, nullptr, nullptr,
            FFD, FFD, DM, DM, 0, 0);
    }

    ln_kernel<<<NTOK, 128>>>(x, h, lnfg, lnfb);

    const long logitsElems = (long)NTOK * VOC;
    float* logits = ((long)out_size >= logitsElems) ? (float*)d_out : lfb;

    tgemm<2,1,0,0,0><<<dim3(VOC / 64, NTOK / 128, 1), 256, SMEM_MT2>>>(
        h, Wout, nullptr, nullptr,
        bout, nullptr, logits, nullptr, nullptr,
        DM, DM, VOC, VOC, 0, 0);

    if ((long)out_size != logitsElems) {
        zero_kernel<<<1, 1>>>(red);
        loss_kernel<<<NTOK, 256>>>(logits, tgts, red);
        float* lossOut;
        if ((long)out_size > logitsElems)
            lossOut = (float*)d_out + logitsElems;
        else
            lossOut = (float*)d_out + (out_size - 1);
        finalize_kernel<<<1, 1>>>(red, lossOut);
    }
}

// round 8
// speedup vs baseline: 1.1307x; 1.0290x over previous
#include <cuda_runtime.h>
#include <math.h>
#include <stdint.h>

// Model dims
#define BT   2
#define TT   2048
#define NTOK 4096
#define DM   512
#define NH   8
#define HSZ  64
#define FFD  2048
#define NL   6
#define VOC  32000

// Scratch
__device__ float g_x [NTOK * DM];
__device__ float g_h [NTOK * DM];
__device__ float g_q [NTOK * DM];
__device__ float g_k [NTOK * DM];
__device__ float g_v [NTOK * DM];
__device__ float g_a [NTOK * DM];
__device__ float g_ff[NTOK * FFD];
__device__ float g_red[2];
__device__ float g_logits_fb[(size_t)NTOK * VOC];

// ---------------------------------------------------------------------------
__device__ __forceinline__ float warpSum(float v) {
#pragma unroll
    for (int o = 16; o > 0; o >>= 1) v += __shfl_xor_sync(0xffffffffu, v, o);
    return v;
}
__device__ __forceinline__ float warpMax(float v) {
#pragma unroll
    for (int o = 16; o > 0; o >>= 1) v = fmaxf(v, __shfl_xor_sync(0xffffffffu, v, o));
    return v;
}

// ---------------------------------------------------------------------------
__global__ void embed_kernel(const int* __restrict__ toks,
                             const float* __restrict__ temb,
                             const float* __restrict__ pemb,
                             float* __restrict__ x) {
    int i = blockIdx.x * blockDim.x + threadIdx.x;
    if (i >= NTOK * DM / 4) return;
    int n  = i / (DM / 4);
    int c  = i % (DM / 4);
    int tk = toks[n];
    int t  = n % TT;
    float4 a = ((const float4*)temb)[(size_t)tk * (DM / 4) + c];
    float4 p = ((const float4*)pemb)[(size_t)t  * (DM / 4) + c];
    float4 r;
    r.x = a.x + p.x; r.y = a.y + p.y; r.z = a.z + p.z; r.w = a.w + p.w;
    ((float4*)x)[i] = r;
}

// ---------------------------------------------------------------------------
__global__ void ln_kernel(const float* __restrict__ in, float* __restrict__ out,
                          const float* __restrict__ gamma, const float* __restrict__ beta) {
    int row = blockIdx.x;
    int tid = threadIdx.x;
    const float4 v4 = ((const float4*)(in + (size_t)row * DM))[tid];
    float s  = v4.x + v4.y + v4.z + v4.w;
    float s2 = v4.x * v4.x + v4.y * v4.y + v4.z * v4.z + v4.w * v4.w;

    __shared__ float rs[4], rs2[4];
    int warp = tid >> 5, lane = tid & 31;
    s = warpSum(s); s2 = warpSum(s2);
    if (lane == 0) { rs[warp] = s; rs2[warp] = s2; }
    __syncthreads();
    float ts = 0.f, ts2 = 0.f;
#pragma unroll
    for (int w = 0; w < 4; w++) { ts += rs[w]; ts2 += rs2[w]; }
    float mean = ts * (1.0f / DM);
    float var  = ts2 * (1.0f / DM) - mean * mean;
    float rstd = rsqrtf(var + 1e-5f);

    float4 g4 = ((const float4*)gamma)[tid];
    float4 b4 = ((const float4*)beta)[tid];
    float4 o;
    o.x = (v4.x - mean) * rstd * g4.x + b4.x;
    o.y = (v4.y - mean) * rstd * g4.y + b4.y;
    o.z = (v4.z - mean) * rstd * g4.z + b4.z;
    o.w = (v4.w - mean) * rstd * g4.w + b4.w;
    ((float4*)(out + (size_t)row * DM))[tid] = o;
}

// ---------------------------------------------------------------------------
// tf32 helpers
// ---------------------------------------------------------------------------
__device__ __forceinline__ void cpa16(uint32_t s, const void* g) {
    asm volatile("cp.async.cg.shared.global [%0], [%1], 16;\n" :: "r"(s), "l"(g));
}

__device__ __forceinline__ unsigned f2tf(float x) {
    unsigned r;
    asm("cvt.rna.tf32.f32 %0, %1;\n" : "=r"(r) : "f"(x));
    return r;
}

__device__ __forceinline__ void mma_u(float (&c)[4], const unsigned (&A)[4], const unsigned (&B)[2]) {
    asm volatile(
        "mma.sync.aligned.m16n8k8.row.col.f32.tf32.tf32.f32 "
        "{%0,%1,%2,%3}, {%4,%5,%6,%7}, {%8,%9}, {%0,%1,%2,%3};\n"
        : "+f"(c[0]), "+f"(c[1]), "+f"(c[2]), "+f"(c[3])
        : "r"(A[0]), "r"(A[1]), "r"(A[2]), "r"(A[3]), "r"(B[0]), "r"(B[1]));
}

__device__ __forceinline__ void split4(const float (&a)[4], unsigned (&h)[4], unsigned (&l)[4]) {
#pragma unroll
    for (int i = 0; i < 4; i++) {
        unsigned hh = f2tf(a[i]);
        h[i] = hh;
        l[i] = f2tf(a[i] - __uint_as_float(hh));
    }
}
__device__ __forceinline__ void split2(const float (&a)[2], unsigned (&h)[2], unsigned (&l)[2]) {
#pragma unroll
    for (int i = 0; i < 2; i++) {
        unsigned hh = f2tf(a[i]);
        h[i] = hh;
        l[i] = f2tf(a[i] - __uint_as_float(hh));
    }
}
__device__ __forceinline__ void splitf(float x, unsigned& h, unsigned& l) {
    h = f2tf(x);
    l = f2tf(x - __uint_as_float(h));
}

// ---------------------------------------------------------------------------
// 3xTF32 tensor-core GEMM (fp32-accurate)
// ---------------------------------------------------------------------------
#define ASTR 36
#define BSTR 72

template<int MT, int BIAS, int RES, int RELU, int QKV>
__global__ void __launch_bounds__(256)
tgemm(const float* __restrict__ A,
      const float* __restrict__ B0, const float* __restrict__ B1, const float* __restrict__ B2,
      const float* __restrict__ bias, const float* __restrict__ res,
      float* __restrict__ C0, float* __restrict__ C1, float* __restrict__ C2,
      int K, int lda, int ldb, int ldc, long bz, long cz) {
    constexpr int BM   = MT * 64;
    constexpr int ABUF = BM * ASTR;
    constexpr int BBUF = 32 * BSTR;

    extern __shared__ float smm[];
    float* sA = smm;
    float* sB = smm + 2 * ABUF;

    const float* B;
    float* C;
    if (QKV) {
        int z = blockIdx.z, sel = z >> 3, head = z & 7;
        const float* Bp = (sel == 0) ? B0 : (sel == 1) ? B1 : B2;
        float*       Cp = (sel == 0) ? C0 : (sel == 1) ? C1 : C2;
        B = Bp + (long)head * bz;
        C = Cp + (long)head * cz;
    } else {
        B = B0 + (long)blockIdx.z * bz;
        C = C0 + (long)blockIdx.z * cz;
    }

    int tid = threadIdx.x;
    int rowBase = blockIdx.y * BM;
    int colBase = blockIdx.x * 64;

    uint32_t sAaddr = (uint32_t)__cvta_generic_to_shared(sA);
    uint32_t sBaddr = (uint32_t)__cvta_generic_to_shared(sB);

    int ntiles = K >> 5;

    {
#pragma unroll
        for (int i = 0; i < 2 * MT; i++) {
            int idx = tid + i * 256;
            int r = idx >> 3, c = (idx & 7) * 4;
            cpa16(sAaddr + (uint32_t)(r * ASTR + c) * 4,
                  A + (size_t)(rowBase + r) * lda + c);
        }
#pragma unroll
        for (int i = 0; i < 2; i++) {
            int idx = tid + i * 256;
            int r = idx >> 4, c = (idx & 15) * 4;
            cpa16(sBaddr + (uint32_t)(r * BSTR + c) * 4,
                  B + (size_t)r * ldb + colBase + c);
        }
        asm volatile("cp.async.commit_group;\n");
    }

    float acc[MT][4][4] = {};
    int lane = tid & 31, warp = tid >> 5;
    int wm = warp >> 1, wn = warp & 1;
    int g = lane >> 2, tg = lane & 3;

    for (int t = 0; t < ntiles; t++) {
        asm volatile("cp.async.wait_group 0;\n");
        __syncthreads();
        int cur = t & 1, nxt = cur ^ 1;

        if (t + 1 < ntiles) {
            int k0 = (t + 1) << 5;
#pragma unroll
            for (int i = 0; i < 2 * MT; i++) {
                int idx = tid + i * 256;
                int r = idx >> 3, c = (idx & 7) * 4;
                cpa16(sAaddr + (uint32_t)(nxt * ABUF + r * ASTR + c) * 4,
                      A + (size_t)(rowBase + r) * lda + k0 + c);
            }
#pragma unroll
            for (int i = 0; i < 2; i++) {
                int idx = tid + i * 256;
                int r = idx >> 4, c = (idx & 15) * 4;
                cpa16(sBaddr + (uint32_t)(nxt * BBUF + r * BSTR + c) * 4,
                      B + (size_t)(k0 + r) * ldb + colBase + c);
            }
            asm volatile("cp.async.commit_group;\n");
        }

        const float* cA = sA + cur * ABUF;
        const float* cB = sB + cur * BBUF;

#pragma unroll
        for (int kk = 0; kk < 4; kk++) {
            float a[MT][4], b[4][2];
#pragma unroll
            for (int mt = 0; mt < MT; mt++) {
                int mb = wm * (MT * 16) + mt * 16;
                a[mt][0] = cA[(mb + g)     * ASTR + kk * 8 + tg];
                a[mt][1] = cA[(mb + 8 + g) * ASTR + kk * 8 + tg];
                a[mt][2] = cA[(mb + g)     * ASTR + kk * 8 + 4 + tg];
                a[mt][3] = cA[(mb + 8 + g) * ASTR + kk * 8 + 4 + tg];
            }
#pragma unroll
            for (int nt = 0; nt < 4; nt++) {
                int nb = wn * 32 + nt * 8;
                b[nt][0] = cB[(kk * 8 + tg)     * BSTR + nb + g];
                b[nt][1] = cB[(kk * 8 + 4 + tg) * BSTR + nb + g];
            }

            unsigned ah[MT][4], al[MT][4], bh[4][2], bl[4][2];
#pragma unroll
            for (int mt = 0; mt < MT; mt++) split4(a[mt], ah[mt], al[mt]);
#pragma unroll
            for (int nt = 0; nt < 4; nt++) split2(b[nt], bh[nt], bl[nt]);

#pragma unroll
            for (int mt = 0; mt < MT; mt++)
#pragma unroll
                for (int nt = 0; nt < 4; nt++) {
                    mma_u(acc[mt][nt], al[mt], bh[nt]);
                    mma_u(acc[mt][nt], ah[mt], bl[nt]);
                    mma_u(acc[mt][nt], ah[mt], bh[nt]);
                }
        }
        __syncthreads();
    }

#pragma unroll
    for (int mt = 0; mt < MT; mt++) {
#pragma unroll
        for (int nt = 0; nt < 4; nt++) {
            int r0 = rowBase + wm * (MT * 16) + mt * 16 + g;
            int c0 = colBase + wn * 32 + nt * 8 + 2 * tg;
            float bx = 0.f, by = 0.f;
            if (BIAS) { bx = bias[c0]; by = bias[c0 + 1]; }
            size_t o0 = (size_t)r0 * ldc + c0;
            size_t o1 = (size_t)(r0 + 8) * ldc + c0;
            float v0 = acc[mt][nt][0] + bx;
            float v1 = acc[mt][nt][1] + by;
            float v2 = acc[mt][nt][2] + bx;
            float v3 = acc[mt][nt][3] + by;
            if (RES) {
                v0 += res[o0]; v1 += res[o0 + 1];
                v2 += res[o1]; v3 += res[o1 + 1];
            }
            if (RELU) {
                v0 = fmaxf(v0, 0.f); v1 = fmaxf(v1, 0.f);
                v2 = fmaxf(v2, 0.f); v3 = fmaxf(v3, 0.f);
            }
            C[o0] = v0; C[o0 + 1] = v1;
            C[o1] = v2; C[o1 + 1] = v3;
        }
    }
}

#define SMEM_MT1 ((2 * (64  * ASTR + 32 * BSTR)) * 4)   // 36864
#define SMEM_MT2 ((2 * (128 * ASTR + 32 * BSTR)) * 4)   // 55296

// ---------------------------------------------------------------------------
// MMA flash attention v2 (3xTF32, hoisted splits):
//   - Q split ONCE into per-warp register fragments (invariant across tiles)
//   - K/V split ONCE per tile at load time into hi/lo SMEM planes
//   - only P splits in the inner loop
// 64 queries/block, 8 warps (4m x 2n). sP aliases the Q staging buffer.
// ---------------------------------------------------------------------------
#define KSTR 68
#define VSTR 72
#define PSTR 68
#define FLASH_SMEM ((64 * PSTR + 2 * 64 * KSTR + 2 * 64 * VSTR + 192) * 4)  // 89856

__global__ void __launch_bounds__(256)
flash_mma(const float* __restrict__ q, const float* __restrict__ k,
          const float* __restrict__ v, float* __restrict__ out) {
    extern __shared__ float sm[];
    float* sP  = sm;                    // 64*PSTR (doubles as Q staging)
    float* sKh = sP  + 64 * PSTR;
    float* sKl = sKh + 64 * KSTR;
    float* sVh = sKl + 64 * KSTR;
    float* sVl = sVh + 64 * VSTR;
    float* sM  = sVl + 64 * VSTR;       // 64
    float* sL  = sM + 64;               // 64
    float* sAl = sL + 64;               // 64

    int qb = blockIdx.x * 64, h = blockIdx.y, b = blockIdx.z;
    int tid = threadIdx.x, lane = tid & 31, warp = tid >> 5;
    int wm = warp >> 1, wn = warp & 1;
    int g = lane >> 2, tg = lane & 3;
    int mb = wm * 16;

    // stage Q (scaled) into sP region
    const float* qp = q + (size_t)(b * TT + qb) * DM + h * HSZ;
    for (int i = tid; i < 64 * 16; i += 256) {
        int r = i >> 4, c = (i & 15) * 4;
        float4 t = *(const float4*)(qp + (size_t)r * DM + c);
        sP[r * PSTR + c + 0] = t.x * 0.125f;
        sP[r * PSTR + c + 1] = t.y * 0.125f;
        sP[r * PSTR + c + 2] = t.z * 0.125f;
        sP[r * PSTR + c + 3] = t.w * 0.125f;
    }
    if (tid < 64) { sM[tid] = -INFINITY; sL[tid] = 0.f; }
    __syncthreads();

    // per-warp Q fragments, split once into registers
    unsigned qh[8][4], ql[8][4];
#pragma unroll
    for (int kk = 0; kk < 8; kk++) {
        float a[4];
        a[0] = sP[(mb + g)     * PSTR + kk * 8 + tg];
        a[1] = sP[(mb + 8 + g) * PSTR + kk * 8 + tg];
        a[2] = sP[(mb + g)     * PSTR + kk * 8 + 4 + tg];
        a[3] = sP[(mb + 8 + g) * PSTR + kk * 8 + 4 + tg];
        split4(a, qh[kk], ql[kk]);
    }

    float accO[4][4] = {};
    int nkt = qb >> 6;

    for (int kt = 0; kt <= nkt; kt++) {
        __syncthreads();  // prior PV reads of sP/sV done; Q frag loads done (kt=0)
        // load K,V tile; split into hi/lo planes at store time
        const float* kp = k + (size_t)(b * TT + kt * 64) * DM + h * HSZ;
        const float* vp = v + (size_t)(b * TT + kt * 64) * DM + h * HSZ;
        for (int i = tid; i < 64 * 16; i += 256) {
            int r = i >> 4, c = (i & 15) * 4;
            float4 tk = *(const float4*)(kp + (size_t)r * DM + c);
            float4 tv = *(const float4*)(vp + (size_t)r * DM + c);
            uint4 kh, klo, vh, vlo;
            splitf(tk.x, kh.x, klo.x); splitf(tk.y, kh.y, klo.y);
            splitf(tk.z, kh.z, klo.z); splitf(tk.w, kh.w, klo.w);
            splitf(tv.x, vh.x, vlo.x); splitf(tv.y, vh.y, vlo.y);
            splitf(tv.z, vh.z, vlo.z); splitf(tv.w, vh.w, vlo.w);
            *(uint4*)(sKh + r * KSTR + c) = kh;
            *(uint4*)(sKl + r * KSTR + c) = klo;
            *(uint4*)(sVh + r * VSTR + c) = vh;
            *(uint4*)(sVl + r * VSTR + c) = vlo;
        }
        __syncthreads();

        // ---- S = Q @ K^T ----
        float accS[4][4] = {};
#pragma unroll
        for (int kk = 0; kk < 8; kk++) {
#pragma unroll
            for (int nt = 0; nt < 4; nt++) {
                int nb = wn * 32 + nt * 8;
                unsigned bh[2], bl[2];
                bh[0] = __float_as_uint(sKh[(nb + g) * KSTR + kk * 8 + tg]);
                bh[1] = __float_as_uint(sKh[(nb + g) * KSTR + kk * 8 + 4 + tg]);
                bl[0] = __float_as_uint(sKl[(nb + g) * KSTR + kk * 8 + tg]);
                bl[1] = __float_as_uint(sKl[(nb + g) * KSTR + kk * 8 + 4 + tg]);
                mma_u(accS[nt], ql[kk], bh);
                mma_u(accS[nt], qh[kk], bl);
                mma_u(accS[nt], qh[kk], bh);
            }
        }

        // write S to sP with causal mask
        bool dg = (kt == nkt);
        int r0 = mb + g, r1 = r0 + 8;
#pragma unroll
        for (int nt = 0; nt < 4; nt++) {
            int c0 = wn * 32 + nt * 8 + 2 * tg;
            float s0 = accS[nt][0], s1 = accS[nt][1];
            float s2 = accS[nt][2], s3 = accS[nt][3];
            if (dg) {
                int qi0 = qb + r0, qi1 = qb + r1, kc = kt * 64 + c0;
                if (kc     > qi0) s0 = -INFINITY;
                if (kc + 1 > qi0) s1 = -INFINITY;
                if (kc     > qi1) s2 = -INFINITY;
                if (kc + 1 > qi1) s3 = -INFINITY;
            }
            sP[r0 * PSTR + c0] = s0; sP[r0 * PSTR + c0 + 1] = s1;
            sP[r1 * PSTR + c0] = s2; sP[r1 * PSTR + c0 + 1] = s3;
        }
        __syncthreads();

        // ---- online softmax: 4 threads per row ----
        {
            int r = tid >> 2, part = tid & 3;
            float* row = sP + r * PSTR + part * 16;
            float m_old = sM[r];
            float mx = m_old;
#pragma unroll
            for (int j = 0; j < 16; j++) mx = fmaxf(mx, row[j]);
            mx = fmaxf(mx, __shfl_xor_sync(0xffffffffu, mx, 1));
            mx = fmaxf(mx, __shfl_xor_sync(0xffffffffu, mx, 2));
            float su = 0.f;
#pragma unroll
            for (int j = 0; j < 16; j++) {
                float p = __expf(row[j] - mx);
                row[j] = p;
                su += p;
            }
            su += __shfl_xor_sync(0xffffffffu, su, 1);
            su += __shfl_xor_sync(0xffffffffu, su, 2);
            if (part == 0) {
                float alv = __expf(m_old - mx);
                sL[r] = sL[r] * alv + su;
                sM[r] = mx;
                sAl[r] = alv;
            }
        }
        __syncthreads();

        // rescale O accumulators
        {
            float a0 = sAl[r0], a1 = sAl[r1];
#pragma unroll
            for (int nt = 0; nt < 4; nt++) {
                accO[nt][0] *= a0; accO[nt][1] *= a0;
                accO[nt][2] *= a1; accO[nt][3] *= a1;
            }
        }

        // ---- O += P @ V (P split in regs, V from planes) ----
#pragma unroll
        for (int kk = 0; kk < 8; kk++) {
            float a[4];
            a[0] = sP[(mb + g)     * PSTR + kk * 8 + tg];
            a[1] = sP[(mb + 8 + g) * PSTR + kk * 8 + tg];
            a[2] = sP[(mb + g)     * PSTR + kk * 8 + 4 + tg];
            a[3] = sP[(mb + 8 + g) * PSTR + kk * 8 + 4 + tg];
            unsigned ah[4], al[4];
            split4(a, ah, al);
#pragma unroll
            for (int nt = 0; nt < 4; nt++) {
                int nb = wn * 32 + nt * 8;
                unsigned bh[2], bl[2];
                bh[0] = __float_as_uint(sVh[(kk * 8 + tg)     * VSTR + nb + g]);
                bh[1] = __float_as_uint(sVh[(kk * 8 + 4 + tg) * VSTR + nb + g]);
                bl[0] = __float_as_uint(sVl[(kk * 8 + tg)     * VSTR + nb + g]);
                bl[1] = __float_as_uint(sVl[(kk * 8 + 4 + tg) * VSTR + nb + g]);
                mma_u(accO[nt], al, bh);
                mma_u(accO[nt], ah, bl);
                mma_u(accO[nt], ah, bh);
            }
        }
    }

    // epilogue: O /= l
    int r0 = mb + g, r1 = r0 + 8;
    float li0 = 1.0f / sL[r0], li1 = 1.0f / sL[r1];
    float* op = out + (size_t)(b * TT + qb) * DM + h * HSZ;
#pragma unroll
    for (int nt = 0; nt < 4; nt++) {
        int c0 = wn * 32 + nt * 8 + 2 * tg;
        op[(size_t)r0 * DM + c0]     = accO[nt][0] * li0;
        op[(size_t)r0 * DM + c0 + 1] = accO[nt][1] * li0;
        op[(size_t)r1 * DM + c0]     = accO[nt][2] * li1;
        op[(size_t)r1 * DM + c0 + 1] = accO[nt][3] * li1;
    }
}

// ---------------------------------------------------------------------------
__global__ void zero_kernel(float* red) { red[0] = 0.f; red[1] = 0.f; }

__global__ void loss_kernel(const float* __restrict__ logits, const int* __restrict__ tgt,
                            float* __restrict__ red) {
    int r = blockIdx.x;
    int tid = threadIdx.x;
    int warp = tid >> 5, lane = tid & 31;
    const float* row = logits + (size_t)r * VOC;
    __shared__ float rbuf[8];

    float lmax = -INFINITY;
    for (int c = tid; c < VOC; c += 256) lmax = fmaxf(lmax, row[c]);
    lmax = warpMax(lmax);
    if (lane == 0) rbuf[warp] = lmax;
    __syncthreads();
    float gmax = -INFINITY;
#pragma unroll
    for (int w = 0; w < 8; w++) gmax = fmaxf(gmax, rbuf[w]);
    __syncthreads();

    float lsum = 0.f;
    for (int c = tid; c < VOC; c += 256) lsum += __expf(row[c] - gmax);
    lsum = warpSum(lsum);
    if (lane == 0) rbuf[warp] = lsum;
    __syncthreads();
    if (tid == 0) {
        float gsum = 0.f;
#pragma unroll
        for (int w = 0; w < 8; w++) gsum += rbuf[w];
        int tg = tgt[r];
        float lp = row[tg] - gmax - logf(gsum);
        float m = (tg != 0) ? 1.0f : 0.0f;
        atomicAdd(&red[0], -lp * m);
        atomicAdd(&red[1], m);
    }
}

__global__ void finalize_kernel(const float* __restrict__ red, float* __restrict__ outp) {
    outp[0] = red[0] / red[1];
}

// ---------------------------------------------------------------------------
extern "C" void kernel_launch(void* const* d_in, const int* in_sizes, int n_in,
                              void* d_out, int out_size) {
    const int*   toks = (const int*)d_in[0];
    const int*   tgts = (const int*)d_in[1];
    const float* temb = (const float*)d_in[2];
    const float* pemb = (const float*)d_in[3];
    const float* Wq   = (const float*)d_in[4];
    const float* Wk   = (const float*)d_in[5];
    const float* Wv   = (const float*)d_in[6];
    const float* Wo   = (const float*)d_in[7];
    const float* bo   = (const float*)d_in[8];
    const float* ln1g = (const float*)d_in[9];
    const float* ln1b = (const float*)d_in[10];
    const float* ln2g = (const float*)d_in[11];
    const float* ln2b = (const float*)d_in[12];
    const float* W1   = (const float*)d_in[13];
    const float* b1   = (const float*)d_in[14];
    const float* W2   = (const float*)d_in[15];
    const float* b2   = (const float*)d_in[16];
    const float* lnfg = (const float*)d_in[17];
    const float* lnfb = (const float*)d_in[18];
    const float* Wout = (const float*)d_in[19];
    const float* bout = (const float*)d_in[20];

    float *x, *h, *q, *k, *v, *a, *ff, *red, *lfb;
    cudaGetSymbolAddress((void**)&x,   g_x);
    cudaGetSymbolAddress((void**)&h,   g_h);
    cudaGetSymbolAddress((void**)&q,   g_q);
    cudaGetSymbolAddress((void**)&k,   g_k);
    cudaGetSymbolAddress((void**)&v,   g_v);
    cudaGetSymbolAddress((void**)&a,   g_a);
    cudaGetSymbolAddress((void**)&ff,  g_ff);
    cudaGetSymbolAddress((void**)&red, g_red);
    cudaGetSymbolAddress((void**)&lfb, g_logits_fb);

    cudaFuncSetAttribute((const void*)tgemm<1,0,0,0,1>, cudaFuncAttributeMaxDynamicSharedMemorySize, SMEM_MT1);
    cudaFuncSetAttribute((const void*)tgemm<1,1,1,0,0>, cudaFuncAttributeMaxDynamicSharedMemorySize, SMEM_MT1);
    cudaFuncSetAttribute((const void*)tgemm<2,1,0,1,0>, cudaFuncAttributeMaxDynamicSharedMemorySize, SMEM_MT2);
    cudaFuncSetAttribute((const void*)tgemm<2,1,0,0,0>, cudaFuncAttributeMaxDynamicSharedMemorySize, SMEM_MT2);
    cudaFuncSetAttribute((const void*)flash_mma,        cudaFuncAttributeMaxDynamicSharedMemorySize, FLASH_SMEM);

    embed_kernel<<<(NTOK * DM / 4 + 255) / 256, 256>>>(toks, temb, pemb, x);

    for (int l = 0; l < NL; l++) {
        ln_kernel<<<NTOK, 128>>>(x, h, ln1g + l * DM, ln1b + l * DM);

        // merged QKV: grid.z = 24 (3 matrices x 8 heads), BM=64
        tgemm<1,0,0,0,1><<<dim3(1, NTOK / 64, 24), 256, SMEM_MT1>>>(
            h,
            Wq + (size_t)l * NH * DM * HSZ,
            Wk + (size_t)l * NH * DM * HSZ,
            Wv + (size_t)l * NH * DM * HSZ,
            nullptr, nullptr,
            q, k, v,
            DM, DM, HSZ, DM, (long)DM * HSZ, HSZ);

        flash_mma<<<dim3(TT / 64, NH, BT), 256, FLASH_SMEM>>>(q, k, v, a);

        // Wo + bias + residual
        tgemm<1,1,1,0,0><<<dim3(DM / 64, NTOK / 64, 1), 256, SMEM_MT1>>>(
            a, Wo + (size_t)l * DM * DM, nullptr, nullptr,
            bo + l * DM, x, x, nullptr, nullptr,
            DM, DM, DM, DM, 0, 0);

        ln_kernel<<<NTOK, 128>>>(x, h, ln2g + l * DM, ln2b + l * DM);

        // FF1 + bias + relu
        tgemm<2,1,0,1,0><<<dim3(FFD / 64, NTOK / 128, 1), 256, SMEM_MT2>>>(
            h, W1 + (size_t)l * DM * FFD, nullptr, nullptr,
            b1 + (size_t)l * FFD, nullptr, ff, nullptr, nullptr,
            DM, DM, FFD, FFD, 0, 0);
        // FF2 + bias + residual
        tgemm<1,1,1,0,0><<<dim3(DM / 64, NTOK / 64, 1), 256, SMEM_MT1>>>(
            ff, W2 + (size_t)l * FFD * DM, nullptr, nullptr,
            b2 + l * DM, x, x, nullptr, nullptr,
            FFD, FFD, DM, DM, 0, 0);
    }

    ln_kernel<<<NTOK, 128>>>(x, h, lnfg, lnfb);

    const long logitsElems = (long)NTOK * VOC;
    float* logits = ((long)out_size >= logitsElems) ? (float*)d_out : lfb;

    tgemm<2,1,0,0,0><<<dim3(VOC / 64, NTOK / 128, 1), 256, SMEM_MT2>>>(
        h, Wout, nullptr, nullptr,
        bout, nullptr, logits, nullptr, nullptr,
        DM, DM, VOC, VOC, 0, 0);

    if ((long)out_size != logitsElems) {
        zero_kernel<<<1, 1>>>(red);
        loss_kernel<<<NTOK, 256>>>(logits, tgts, red);
        float* lossOut;
        if ((long)out_size > logitsElems)
            lossOut = (float*)d_out + logitsElems;
        else
            lossOut = (float*)d_out + (out_size - 1);
        finalize_kernel<<<1, 1>>>(red, lossOut);
    }
}

// round 9
// speedup vs baseline: 1.1326x; 1.0017x over previous
#include <cuda_runtime.h>
#include <math.h>
#include <stdint.h>

// Model dims
#define BT   2
#define TT   2048
#define NTOK 4096
#define DM   512
#define NH   8
#define HSZ  64
#define FFD  2048
#define NL   6
#define VOC  32000

// Scratch
__device__ float g_x [NTOK * DM];
__device__ float g_h [NTOK * DM];
__device__ float g_q [NTOK * DM];
__device__ float g_k [NTOK * DM];
__device__ float g_v [NTOK * DM];
__device__ float g_a [NTOK * DM];
__device__ float g_ff[NTOK * FFD];
__device__ float g_red[2];
__device__ float g_logits_fb[(size_t)NTOK * VOC];

// ---------------------------------------------------------------------------
__device__ __forceinline__ float warpSum(float v) {
#pragma unroll
    for (int o = 16; o > 0; o >>= 1) v += __shfl_xor_sync(0xffffffffu, v, o);
    return v;
}
__device__ __forceinline__ float warpMax(float v) {
#pragma unroll
    for (int o = 16; o > 0; o >>= 1) v = fmaxf(v, __shfl_xor_sync(0xffffffffu, v, o));
    return v;
}

// ---------------------------------------------------------------------------
__global__ void embed_kernel(const int* __restrict__ toks,
                             const float* __restrict__ temb,
                             const float* __restrict__ pemb,
                             float* __restrict__ x) {
    int i = blockIdx.x * blockDim.x + threadIdx.x;
    if (i >= NTOK * DM / 4) return;
    int n  = i / (DM / 4);
    int c  = i % (DM / 4);
    int tk = toks[n];
    int t  = n % TT;
    float4 a = ((const float4*)temb)[(size_t)tk * (DM / 4) + c];
    float4 p = ((const float4*)pemb)[(size_t)t  * (DM / 4) + c];
    float4 r;
    r.x = a.x + p.x; r.y = a.y + p.y; r.z = a.z + p.z; r.w = a.w + p.w;
    ((float4*)x)[i] = r;
}

// ---------------------------------------------------------------------------
__global__ void ln_kernel(const float* __restrict__ in, float* __restrict__ out,
                          const float* __restrict__ gamma, const float* __restrict__ beta) {
    int row = blockIdx.x;
    int tid = threadIdx.x;
    const float4 v4 = ((const float4*)(in + (size_t)row * DM))[tid];
    float s  = v4.x + v4.y + v4.z + v4.w;
    float s2 = v4.x * v4.x + v4.y * v4.y + v4.z * v4.z + v4.w * v4.w;

    __shared__ float rs[4], rs2[4];
    int warp = tid >> 5, lane = tid & 31;
    s = warpSum(s); s2 = warpSum(s2);
    if (lane == 0) { rs[warp] = s; rs2[warp] = s2; }
    __syncthreads();
    float ts = 0.f, ts2 = 0.f;
#pragma unroll
    for (int w = 0; w < 4; w++) { ts += rs[w]; ts2 += rs2[w]; }
    float mean = ts * (1.0f / DM);
    float var  = ts2 * (1.0f / DM) - mean * mean;
    float rstd = rsqrtf(var + 1e-5f);

    float4 g4 = ((const float4*)gamma)[tid];
    float4 b4 = ((const float4*)beta)[tid];
    float4 o;
    o.x = (v4.x - mean) * rstd * g4.x + b4.x;
    o.y = (v4.y - mean) * rstd * g4.y + b4.y;
    o.z = (v4.z - mean) * rstd * g4.z + b4.z;
    o.w = (v4.w - mean) * rstd * g4.w + b4.w;
    ((float4*)(out + (size_t)row * DM))[tid] = o;
}

// ---------------------------------------------------------------------------
// tf32 helpers
// ---------------------------------------------------------------------------
__device__ __forceinline__ void cpa16(uint32_t s, const void* g) {
    asm volatile("cp.async.cg.shared.global [%0], [%1], 16;\n" :: "r"(s), "l"(g));
}

__device__ __forceinline__ unsigned f2tf(float x) {
    unsigned r;
    asm("cvt.rna.tf32.f32 %0, %1;\n" : "=r"(r) : "f"(x));
    return r;
}

__device__ __forceinline__ void mma_u(float (&c)[4], const unsigned (&A)[4], const unsigned (&B)[2]) {
    asm volatile(
        "mma.sync.aligned.m16n8k8.row.col.f32.tf32.tf32.f32 "
        "{%0,%1,%2,%3}, {%4,%5,%6,%7}, {%8,%9}, {%0,%1,%2,%3};\n"
        : "+f"(c[0]), "+f"(c[1]), "+f"(c[2]), "+f"(c[3])
        : "r"(A[0]), "r"(A[1]), "r"(A[2]), "r"(A[3]), "r"(B[0]), "r"(B[1]));
}

__device__ __forceinline__ void split4(const float (&a)[4], unsigned (&h)[4], unsigned (&l)[4]) {
#pragma unroll
    for (int i = 0; i < 4; i++) {
        unsigned hh = f2tf(a[i]);
        h[i] = hh;
        l[i] = f2tf(a[i] - __uint_as_float(hh));
    }
}
__device__ __forceinline__ void split2(const float (&a)[2], unsigned (&h)[2], unsigned (&l)[2]) {
#pragma unroll
    for (int i = 0; i < 2; i++) {
        unsigned hh = f2tf(a[i]);
        h[i] = hh;
        l[i] = f2tf(a[i] - __uint_as_float(hh));
    }
}
__device__ __forceinline__ void splitf(float x, unsigned& h, unsigned& l) {
    h = f2tf(x);
    l = f2tf(x - __uint_as_float(h));
}

// ---------------------------------------------------------------------------
// 3xTF32 tensor-core GEMM (fp32-accurate)
// ---------------------------------------------------------------------------
#define ASTR 36
#define BSTR 72

template<int MT, int BIAS, int RES, int RELU, int QKV>
__global__ void __launch_bounds__(256)
tgemm(const float* __restrict__ A,
      const float* __restrict__ B0, const float* __restrict__ B1, const float* __restrict__ B2,
      const float* __restrict__ bias, const float* __restrict__ res,
      float* __restrict__ C0, float* __restrict__ C1, float* __restrict__ C2,
      int K, int lda, int ldb, int ldc, long bz, long cz) {
    constexpr int BM   = MT * 64;
    constexpr int ABUF = BM * ASTR;
    constexpr int BBUF = 32 * BSTR;

    extern __shared__ float smm[];
    float* sA = smm;
    float* sB = smm + 2 * ABUF;

    const float* B;
    float* C;
    if (QKV) {
        int z = blockIdx.z, sel = z >> 3, head = z & 7;
        const float* Bp = (sel == 0) ? B0 : (sel == 1) ? B1 : B2;
        float*       Cp = (sel == 0) ? C0 : (sel == 1) ? C1 : C2;
        B = Bp + (long)head * bz;
        C = Cp + (long)head * cz;
    } else {
        B = B0 + (long)blockIdx.z * bz;
        C = C0 + (long)blockIdx.z * cz;
    }

    int tid = threadIdx.x;
    int rowBase = blockIdx.y * BM;
    int colBase = blockIdx.x * 64;

    uint32_t sAaddr = (uint32_t)__cvta_generic_to_shared(sA);
    uint32_t sBaddr = (uint32_t)__cvta_generic_to_shared(sB);

    int ntiles = K >> 5;

    {
#pragma unroll
        for (int i = 0; i < 2 * MT; i++) {
            int idx = tid + i * 256;
            int r = idx >> 3, c = (idx & 7) * 4;
            cpa16(sAaddr + (uint32_t)(r * ASTR + c) * 4,
                  A + (size_t)(rowBase + r) * lda + c);
        }
#pragma unroll
        for (int i = 0; i < 2; i++) {
            int idx = tid + i * 256;
            int r = idx >> 4, c = (idx & 15) * 4;
            cpa16(sBaddr + (uint32_t)(r * BSTR + c) * 4,
                  B + (size_t)r * ldb + colBase + c);
        }
        asm volatile("cp.async.commit_group;\n");
    }

    float acc[MT][4][4] = {};
    int lane = tid & 31, warp = tid >> 5;
    int wm = warp >> 1, wn = warp & 1;
    int g = lane >> 2, tg = lane & 3;

    for (int t = 0; t < ntiles; t++) {
        asm volatile("cp.async.wait_group 0;\n");
        __syncthreads();
        int cur = t & 1, nxt = cur ^ 1;

        if (t + 1 < ntiles) {
            int k0 = (t + 1) << 5;
#pragma unroll
            for (int i = 0; i < 2 * MT; i++) {
                int idx = tid + i * 256;
                int r = idx >> 3, c = (idx & 7) * 4;
                cpa16(sAaddr + (uint32_t)(nxt * ABUF + r * ASTR + c) * 4,
                      A + (size_t)(rowBase + r) * lda + k0 + c);
            }
#pragma unroll
            for (int i = 0; i < 2; i++) {
                int idx = tid + i * 256;
                int r = idx >> 4, c = (idx & 15) * 4;
                cpa16(sBaddr + (uint32_t)(nxt * BBUF + r * BSTR + c) * 4,
                      B + (size_t)(k0 + r) * ldb + colBase + c);
            }
            asm volatile("cp.async.commit_group;\n");
        }

        const float* cA = sA + cur * ABUF;
        const float* cB = sB + cur * BBUF;

#pragma unroll
        for (int kk = 0; kk < 4; kk++) {
            float a[MT][4], b[4][2];
#pragma unroll
            for (int mt = 0; mt < MT; mt++) {
                int mb = wm * (MT * 16) + mt * 16;
                a[mt][0] = cA[(mb + g)     * ASTR + kk * 8 + tg];
                a[mt][1] = cA[(mb + 8 + g) * ASTR + kk * 8 + tg];
                a[mt][2] = cA[(mb + g)     * ASTR + kk * 8 + 4 + tg];
                a[mt][3] = cA[(mb + 8 + g) * ASTR + kk * 8 + 4 + tg];
            }
#pragma unroll
            for (int nt = 0; nt < 4; nt++) {
                int nb = wn * 32 + nt * 8;
                b[nt][0] = cB[(kk * 8 + tg)     * BSTR + nb + g];
                b[nt][1] = cB[(kk * 8 + 4 + tg) * BSTR + nb + g];
            }

            unsigned ah[MT][4], al[MT][4], bh[4][2], bl[4][2];
#pragma unroll
            for (int mt = 0; mt < MT; mt++) split4(a[mt], ah[mt], al[mt]);
#pragma unroll
            for (int nt = 0; nt < 4; nt++) split2(b[nt], bh[nt], bl[nt]);

#pragma unroll
            for (int mt = 0; mt < MT; mt++)
#pragma unroll
                for (int nt = 0; nt < 4; nt++) {
                    mma_u(acc[mt][nt], al[mt], bh[nt]);
                    mma_u(acc[mt][nt], ah[mt], bl[nt]);
                    mma_u(acc[mt][nt], ah[mt], bh[nt]);
                }
        }
        __syncthreads();
    }

#pragma unroll
    for (int mt = 0; mt < MT; mt++) {
#pragma unroll
        for (int nt = 0; nt < 4; nt++) {
            int r0 = rowBase + wm * (MT * 16) + mt * 16 + g;
            int c0 = colBase + wn * 32 + nt * 8 + 2 * tg;
            float bx = 0.f, by = 0.f;
            if (BIAS) { bx = bias[c0]; by = bias[c0 + 1]; }
            size_t o0 = (size_t)r0 * ldc + c0;
            size_t o1 = (size_t)(r0 + 8) * ldc + c0;
            float v0 = acc[mt][nt][0] + bx;
            float v1 = acc[mt][nt][1] + by;
            float v2 = acc[mt][nt][2] + bx;
            float v3 = acc[mt][nt][3] + by;
            if (RES) {
                v0 += res[o0]; v1 += res[o0 + 1];
                v2 += res[o1]; v3 += res[o1 + 1];
            }
            if (RELU) {
                v0 = fmaxf(v0, 0.f); v1 = fmaxf(v1, 0.f);
                v2 = fmaxf(v2, 0.f); v3 = fmaxf(v3, 0.f);
            }
            C[o0] = v0; C[o0 + 1] = v1;
            C[o1] = v2; C[o1 + 1] = v3;
        }
    }
}

#define SMEM_MT1 ((2 * (64  * ASTR + 32 * BSTR)) * 4)   // 36864
#define SMEM_MT2 ((2 * (128 * ASTR + 32 * BSTR)) * 4)   // 55296

// ---------------------------------------------------------------------------
// MMA flash attention v2 (3xTF32, hoisted splits):
//   - Q split ONCE into per-warp register fragments (invariant across tiles)
//   - K/V split ONCE per tile at load time into hi/lo SMEM planes
//   - only P splits in the inner loop
// 64 queries/block, 8 warps (4m x 2n). sP aliases the Q staging buffer.
// ---------------------------------------------------------------------------
#define KSTR 68
#define VSTR 72
#define PSTR 68
#define FLASH_SMEM ((64 * PSTR + 2 * 64 * KSTR + 2 * 64 * VSTR + 192) * 4)  // 89856

__global__ void __launch_bounds__(256)
flash_mma(const float* __restrict__ q, const float* __restrict__ k,
          const float* __restrict__ v, float* __restrict__ out) {
    extern __shared__ float sm[];
    float* sP  = sm;                    // 64*PSTR (doubles as Q staging)
    float* sKh = sP  + 64 * PSTR;
    float* sKl = sKh + 64 * KSTR;
    float* sVh = sKl + 64 * KSTR;
    float* sVl = sVh + 64 * VSTR;
    float* sM  = sVl + 64 * VSTR;       // 64
    float* sL  = sM + 64;               // 64
    float* sAl = sL + 64;               // 64

    int qb = blockIdx.x * 64, h = blockIdx.y, b = blockIdx.z;
    int tid = threadIdx.x, lane = tid & 31, warp = tid >> 5;
    int wm = warp >> 1, wn = warp & 1;
    int g = lane >> 2, tg = lane & 3;
    int mb = wm * 16;

    // stage Q (scaled) into sP region
    const float* qp = q + (size_t)(b * TT + qb) * DM + h * HSZ;
    for (int i = tid; i < 64 * 16; i += 256) {
        int r = i >> 4, c = (i & 15) * 4;
        float4 t = *(const float4*)(qp + (size_t)r * DM + c);
        sP[r * PSTR + c + 0] = t.x * 0.125f;
        sP[r * PSTR + c + 1] = t.y * 0.125f;
        sP[r * PSTR + c + 2] = t.z * 0.125f;
        sP[r * PSTR + c + 3] = t.w * 0.125f;
    }
    if (tid < 64) { sM[tid] = -INFINITY; sL[tid] = 0.f; }
    __syncthreads();

    // per-warp Q fragments, split once into registers
    unsigned qh[8][4], ql[8][4];
#pragma unroll
    for (int kk = 0; kk < 8; kk++) {
        float a[4];
        a[0] = sP[(mb + g)     * PSTR + kk * 8 + tg];
        a[1] = sP[(mb + 8 + g) * PSTR + kk * 8 + tg];
        a[2] = sP[(mb + g)     * PSTR + kk * 8 + 4 + tg];
        a[3] = sP[(mb + 8 + g) * PSTR + kk * 8 + 4 + tg];
        split4(a, qh[kk], ql[kk]);
    }

    float accO[4][4] = {};
    int nkt = qb >> 6;

    for (int kt = 0; kt <= nkt; kt++) {
        __syncthreads();  // prior PV reads of sP/sV done; Q frag loads done (kt=0)
        // load K,V tile; split into hi/lo planes at store time
        const float* kp = k + (size_t)(b * TT + kt * 64) * DM + h * HSZ;
        const float* vp = v + (size_t)(b * TT + kt * 64) * DM + h * HSZ;
        for (int i = tid; i < 64 * 16; i += 256) {
            int r = i >> 4, c = (i & 15) * 4;
            float4 tk = *(const float4*)(kp + (size_t)r * DM + c);
            float4 tv = *(const float4*)(vp + (size_t)r * DM + c);
            uint4 kh, klo, vh, vlo;
            splitf(tk.x, kh.x, klo.x); splitf(tk.y, kh.y, klo.y);
            splitf(tk.z, kh.z, klo.z); splitf(tk.w, kh.w, klo.w);
            splitf(tv.x, vh.x, vlo.x); splitf(tv.y, vh.y, vlo.y);
            splitf(tv.z, vh.z, vlo.z); splitf(tv.w, vh.w, vlo.w);
            *(uint4*)(sKh + r * KSTR + c) = kh;
            *(uint4*)(sKl + r * KSTR + c) = klo;
            *(uint4*)(sVh + r * VSTR + c) = vh;
            *(uint4*)(sVl + r * VSTR + c) = vlo;
        }
        __syncthreads();

        // ---- S = Q @ K^T ----
        float accS[4][4] = {};
#pragma unroll
        for (int kk = 0; kk < 8; kk++) {
#pragma unroll
            for (int nt = 0; nt < 4; nt++) {
                int nb = wn * 32 + nt * 8;
                unsigned bh[2], bl[2];
                bh[0] = __float_as_uint(sKh[(nb + g) * KSTR + kk * 8 + tg]);
                bh[1] = __float_as_uint(sKh[(nb + g) * KSTR + kk * 8 + 4 + tg]);
                bl[0] = __float_as_uint(sKl[(nb + g) * KSTR + kk * 8 + tg]);
                bl[1] = __float_as_uint(sKl[(nb + g) * KSTR + kk * 8 + 4 + tg]);
                mma_u(accS[nt], ql[kk], bh);
                mma_u(accS[nt], qh[kk], bl);
                mma_u(accS[nt], qh[kk], bh);
            }
        }

        // write S to sP with causal mask
        bool dg = (kt == nkt);
        int r0 = mb + g, r1 = r0 + 8;
#pragma unroll
        for (int nt = 0; nt < 4; nt++) {
            int c0 = wn * 32 + nt * 8 + 2 * tg;
            float s0 = accS[nt][0], s1 = accS[nt][1];
            float s2 = accS[nt][2], s3 = accS[nt][3];
            if (dg) {
                int qi0 = qb + r0, qi1 = qb + r1, kc = kt * 64 + c0;
                if (kc     > qi0) s0 = -INFINITY;
                if (kc + 1 > qi0) s1 = -INFINITY;
                if (kc     > qi1) s2 = -INFINITY;
                if (kc + 1 > qi1) s3 = -INFINITY;
            }
            sP[r0 * PSTR + c0] = s0; sP[r0 * PSTR + c0 + 1] = s1;
            sP[r1 * PSTR + c0] = s2; sP[r1 * PSTR + c0 + 1] = s3;
        }
        __syncthreads();

        // ---- online softmax: 4 threads per row ----
        {
            int r = tid >> 2, part = tid & 3;
            float* row = sP + r * PSTR + part * 16;
            float m_old = sM[r];
            float mx = m_old;
#pragma unroll
            for (int j = 0; j < 16; j++) mx = fmaxf(mx, row[j]);
            mx = fmaxf(mx, __shfl_xor_sync(0xffffffffu, mx, 1));
            mx = fmaxf(mx, __shfl_xor_sync(0xffffffffu, mx, 2));
            float su = 0.f;
#pragma unroll
            for (int j = 0; j < 16; j++) {
                float p = __expf(row[j] - mx);
                row[j] = p;
                su += p;
            }
            su += __shfl_xor_sync(0xffffffffu, su, 1);
            su += __shfl_xor_sync(0xffffffffu, su, 2);
            if (part == 0) {
                float alv = __expf(m_old - mx);
                sL[r] = sL[r] * alv + su;
                sM[r] = mx;
                sAl[r] = alv;
            }
        }
        __syncthreads();

        // rescale O accumulators
        {
            float a0 = sAl[r0], a1 = sAl[r1];
#pragma unroll
            for (int nt = 0; nt < 4; nt++) {
                accO[nt][0] *= a0; accO[nt][1] *= a0;
                accO[nt][2] *= a1; accO[nt][3] *= a1;
            }
        }

        // ---- O += P @ V (P split in regs, V from planes) ----
#pragma unroll
        for (int kk = 0; kk < 8; kk++) {
            float a[4];
            a[0] = sP[(mb + g)     * PSTR + kk * 8 + tg];
            a[1] = sP[(mb + 8 + g) * PSTR + kk * 8 + tg];
            a[2] = sP[(mb + g)     * PSTR + kk * 8 + 4 + tg];
            a[3] = sP[(mb + 8 + g) * PSTR + kk * 8 + 4 + tg];
            unsigned ah[4], al[4];
            split4(a, ah, al);
#pragma unroll
            for (int nt = 0; nt < 4; nt++) {
                int nb = wn * 32 + nt * 8;
                unsigned bh[2], bl[2];
                bh[0] = __float_as_uint(sVh[(kk * 8 + tg)     * VSTR + nb + g]);
                bh[1] = __float_as_uint(sVh[(kk * 8 + 4 + tg) * VSTR + nb + g]);
                bl[0] = __float_as_uint(sVl[(kk * 8 + tg)     * VSTR + nb + g]);
                bl[1] = __float_as_uint(sVl[(kk * 8 + 4 + tg) * VSTR + nb + g]);
                mma_u(accO[nt], al, bh);
                mma_u(accO[nt], ah, bl);
                mma_u(accO[nt], ah, bh);
            }
        }
    }

    // epilogue: O /= l
    int r0 = mb + g, r1 = r0 + 8;
    float li0 = 1.0f / sL[r0], li1 = 1.0f / sL[r1];
    float* op = out + (size_t)(b * TT + qb) * DM + h * HSZ;
#pragma unroll
    for (int nt = 0; nt < 4; nt++) {
        int c0 = wn * 32 + nt * 8 + 2 * tg;
        op[(size_t)r0 * DM + c0]     = accO[nt][0] * li0;
        op[(size_t)r0 * DM + c0 + 1] = accO[nt][1] * li0;
        op[(size_t)r1 * DM + c0]     = accO[nt][2] * li1;
        op[(size_t)r1 * DM + c0 + 1] = accO[nt][3] * li1;
    }
}

// ---------------------------------------------------------------------------
__global__ void zero_kernel(float* red) { red[0] = 0.f; red[1] = 0.f; }

__global__ void loss_kernel(const float* __restrict__ logits, const int* __restrict__ tgt,
                            float* __restrict__ red) {
    int r = blockIdx.x;
    int tid = threadIdx.x;
    int warp = tid >> 5, lane = tid & 31;
    const float* row = logits + (size_t)r * VOC;
    __shared__ float rbuf[8];

    float lmax = -INFINITY;
    for (int c = tid; c < VOC; c += 256) lmax = fmaxf(lmax, row[c]);
    lmax = warpMax(lmax);
    if (lane == 0) rbuf[warp] = lmax;
    __syncthreads();
    float gmax = -INFINITY;
#pragma unroll
    for (int w = 0; w < 8; w++) gmax = fmaxf(gmax, rbuf[w]);
    __syncthreads();

    float lsum = 0.f;
    for (int c = tid; c < VOC; c += 256) lsum += __expf(row[c] - gmax);
    lsum = warpSum(lsum);
    if (lane == 0) rbuf[warp] = lsum;
    __syncthreads();
    if (tid == 0) {
        float gsum = 0.f;
#pragma unroll
        for (int w = 0; w < 8; w++) gsum += rbuf[w];
        int tg = tgt[r];
        float lp = row[tg] - gmax - logf(gsum);
        float m = (tg != 0) ? 1.0f : 0.0f;
        atomicAdd(&red[0], -lp * m);
        atomicAdd(&red[1], m);
    }
}

__global__ void finalize_kernel(const float* __restrict__ red, float* __restrict__ outp) {
    outp[0] = red[0] / red[1];
}

// ---------------------------------------------------------------------------
extern "C" void kernel_launch(void* const* d_in, const int* in_sizes, int n_in,
                              void* d_out, int out_size) {
    const int*   toks = (const int*)d_in[0];
    const int*   tgts = (const int*)d_in[1];
    const float* temb = (const float*)d_in[2];
    const float* pemb = (const float*)d_in[3];
    const float* Wq   = (const float*)d_in[4];
    const float* Wk   = (const float*)d_in[5];
    const float* Wv   = (const float*)d_in[6];
    const float* Wo   = (const float*)d_in[7];
    const float* bo   = (const float*)d_in[8];
    const float* ln1g = (const float*)d_in[9];
    const float* ln1b = (const float*)d_in[10];
    const float* ln2g = (const float*)d_in[11];
    const float* ln2b = (const float*)d_in[12];
    const float* W1   = (const float*)d_in[13];
    const float* b1   = (const float*)d_in[14];
    const float* W2   = (const float*)d_in[15];
    const float* b2   = (const float*)d_in[16];
    const float* lnfg = (const float*)d_in[17];
    const float* lnfb = (const float*)d_in[18];
    const float* Wout = (const float*)d_in[19];
    const float* bout = (const float*)d_in[20];

    float *x, *h, *q, *k, *v, *a, *ff, *red, *lfb;
    cudaGetSymbolAddress((void**)&x,   g_x);
    cudaGetSymbolAddress((void**)&h,   g_h);
    cudaGetSymbolAddress((void**)&q,   g_q);
    cudaGetSymbolAddress((void**)&k,   g_k);
    cudaGetSymbolAddress((void**)&v,   g_v);
    cudaGetSymbolAddress((void**)&a,   g_a);
    cudaGetSymbolAddress((void**)&ff,  g_ff);
    cudaGetSymbolAddress((void**)&red, g_red);
    cudaGetSymbolAddress((void**)&lfb, g_logits_fb);

    cudaFuncSetAttribute((const void*)tgemm<1,0,0,0,1>, cudaFuncAttributeMaxDynamicSharedMemorySize, SMEM_MT1);
    cudaFuncSetAttribute((const void*)tgemm<1,1,1,0,0>, cudaFuncAttributeMaxDynamicSharedMemorySize, SMEM_MT1);
    cudaFuncSetAttribute((const void*)tgemm<2,1,0,1,0>, cudaFuncAttributeMaxDynamicSharedMemorySize, SMEM_MT2);
    cudaFuncSetAttribute((const void*)tgemm<2,1,0,0,0>, cudaFuncAttributeMaxDynamicSharedMemorySize, SMEM_MT2);
    cudaFuncSetAttribute((const void*)flash_mma,        cudaFuncAttributeMaxDynamicSharedMemorySize, FLASH_SMEM);

    embed_kernel<<<(NTOK * DM / 4 + 255) / 256, 256>>>(toks, temb, pemb, x);

    for (int l = 0; l < NL; l++) {
        ln_kernel<<<NTOK, 128>>>(x, h, ln1g + l * DM, ln1b + l * DM);

        // merged QKV: grid.z = 24 (3 matrices x 8 heads), BM=64
        tgemm<1,0,0,0,1><<<dim3(1, NTOK / 64, 24), 256, SMEM_MT1>>>(
            h,
            Wq + (size_t)l * NH * DM * HSZ,
            Wk + (size_t)l * NH * DM * HSZ,
            Wv + (size_t)l * NH * DM * HSZ,
            nullptr, nullptr,
            q, k, v,
            DM, DM, HSZ, DM, (long)DM * HSZ, HSZ);

        flash_mma<<<dim3(TT / 64, NH, BT), 256, FLASH_SMEM>>>(q, k, v, a);

        // Wo + bias + residual
        tgemm<1,1,1,0,0><<<dim3(DM / 64, NTOK / 64, 1), 256, SMEM_MT1>>>(
            a, Wo + (size_t)l * DM * DM, nullptr, nullptr,
            bo + l * DM, x, x, nullptr, nullptr,
            DM, DM, DM, DM, 0, 0);

        ln_kernel<<<NTOK, 128>>>(x, h, ln2g + l * DM, ln2b + l * DM);

        // FF1 + bias + relu
        tgemm<2,1,0,1,0><<<dim3(FFD / 64, NTOK / 128, 1), 256, SMEM_MT2>>>(
            h, W1 + (size_t)l * DM * FFD, nullptr, nullptr,
            b1 + (size_t)l * FFD, nullptr, ff, nullptr, nullptr,
            DM, DM, FFD, FFD, 0, 0);
        // FF2 + bias + residual
        tgemm<1,1,1,0,0><<<dim3(DM / 64, NTOK / 64, 1), 256, SMEM_MT1>>>(
            ff, W2 + (size_t)l * FFD * DM, nullptr, nullptr,
            b2 + l * DM, x, x, nullptr, nullptr,
            FFD, FFD, DM, DM, 0, 0);
    }

    ln_kernel<<<NTOK, 128>>>(x, h, lnfg, lnfb);

    const long logitsElems = (long)NTOK * VOC;
    float* logits = ((long)out_size >= logitsElems) ? (float*)d_out : lfb;

    tgemm<2,1,0,0,0><<<dim3(VOC / 64, NTOK / 128, 1), 256, SMEM_MT2>>>(
        h, Wout, nullptr, nullptr,
        bout, nullptr, logits, nullptr, nullptr,
        DM, DM, VOC, VOC, 0, 0);

    if ((long)out_size != logitsElems) {
        zero_kernel<<<1, 1>>>(red);
        loss_kernel<<<NTOK, 256>>>(logits, tgts, red);
        float* lossOut;
        if ((long)out_size > logitsElems)
            lossOut = (float*)d_out + logitsElems;
        else
            lossOut = (float*)d_out + (out_size - 1);
        finalize_kernel<<<1, 1>>>(red, lossOut);
    }
}